// round 1
// baseline (speedup 1.0000x reference)
#include <cuda_runtime.h>
#include <cstdio>

#define NN 2048
#define NELEM (2048*2048)

// ---------------- device scratch (no allocations allowed) ----------------
__device__ float g_M[NELEM];   // M = I - A
__device__ float g_X[NELEM];   // Newton iterate
__device__ float g_T[NELEM];   // temp / final W
__device__ float g_Y[NELEM];   // Newton ping-pong
__device__ float g_v[NN];
__device__ float g_u[NN];
__device__ float g_s[4];       // [2] = c scaling

// ---------------- build M = I - (w - w^T) ----------------
__global__ void build_M_kernel(const float* __restrict__ w) {
    int j = blockIdx.x * blockDim.x + threadIdx.x;
    int i = blockIdx.y;
    if (j < NN) {
        float a = w[(size_t)i * NN + j] - w[(size_t)j * NN + i];
        g_M[(size_t)i * NN + j] = (i == j ? 1.0f : 0.0f) - a;
    }
}

__global__ void init_v_kernel() {
    int i = blockIdx.x * blockDim.x + threadIdx.x;
    if (i < NN) {
        unsigned h = (unsigned)i * 2654435761u;
        h ^= h >> 16; h *= 2246822519u; h ^= h >> 13;
        g_v[i] = ((h & 0xFFFFFF) / 16777216.0f) - 0.5f;
    }
}

// out = scale * (in - M @ in)   (== scale * A @ in, since A = I - M)
// dst_is_u: 1 -> u = f(v), 0 -> v = f(u)
__global__ void matvec_A_kernel(int dst_is_u, float scale) {
    __shared__ float red[256];
    const float* in  = dst_is_u ? g_v : g_u;
    float*       out = dst_is_u ? g_u : g_v;
    int row = blockIdx.x;
    const float* Mrow = g_M + (size_t)row * NN;
    float s = 0.f;
    for (int j = threadIdx.x; j < NN; j += 256)
        s += Mrow[j] * in[j];
    red[threadIdx.x] = s;
    __syncthreads();
    for (int off = 128; off > 0; off >>= 1) {
        if (threadIdx.x < off) red[threadIdx.x] += red[threadIdx.x + off];
        __syncthreads();
    }
    if (threadIdx.x == 0)
        out[row] = scale * (in[row] - red[0]);
}

// sigma^2 = (u.u)/(v.v); c = 2 / (2 + 1.25*sigma^2)
__global__ void dots_and_c_kernel() {
    __shared__ float r0[1024], r1[1024];
    int t = threadIdx.x;
    float a = 0.f, b = 0.f;
    for (int i = t; i < NN; i += 1024) {
        float vv = g_v[i], uu = g_u[i];
        a += vv * vv; b += uu * uu;
    }
    r0[t] = a; r1[t] = b;
    __syncthreads();
    for (int off = 512; off > 0; off >>= 1) {
        if (t < off) { r0[t] += r0[t + off]; r1[t] += r1[t + off]; }
        __syncthreads();
    }
    if (t == 0) {
        float sigma2 = r1[0] / (r0[0] + 1e-30f);
        float bb = 1.0f + 1.25f * sigma2;
        g_s[2] = 2.0f / (1.0f + bb);
    }
}

// X0 = c * M^T  (tiled transpose)
__global__ void init_X0_kernel() {
    __shared__ float tile[32][33];
    int bx = blockIdx.x * 32, by = blockIdx.y * 32;
    int x = bx + threadIdx.x;
    #pragma unroll
    for (int dy = 0; dy < 32; dy += 8)
        tile[threadIdx.y + dy][threadIdx.x] = g_M[(size_t)(by + threadIdx.y + dy) * NN + x];
    __syncthreads();
    float c = g_s[2];
    int ox = by + threadIdx.x;
    #pragma unroll
    for (int dy = 0; dy < 32; dy += 8)
        g_X[(size_t)(bx + threadIdx.y + dy) * NN + ox] = c * tile[threadIdx.x][threadIdx.y + dy];
}

// ---------------- fp32 SIMT GEMM ----------------
// C = alpha * A @ op(B) + beta * D (+ bias)
// A: Mdim x Kdim row-major. B: (Kdim x Ndim) if !TRANSB, (Ndim x Kdim) if TRANSB.
// All dims multiples of 128. BM=BN=128, BK=16, 256 threads, 8x8 per thread.
template<bool TRANSB, bool BIAS>
__global__ void __launch_bounds__(256, 2) gemm_kernel(
    float* __restrict__ C, const float* __restrict__ A, const float* __restrict__ B,
    const float* __restrict__ D, const float* __restrict__ bias,
    int Mdim, int Ndim, int Kdim, float alpha, float beta)
{
    __shared__ float As[16][128];
    __shared__ float Bs[16][128];
    int tid = threadIdx.x;
    int bm = blockIdx.y * 128;
    int bn = blockIdx.x * 128;
    int ty = tid >> 4, tx = tid & 15;
    float acc[8][8];
    #pragma unroll
    for (int i = 0; i < 8; i++)
        #pragma unroll
        for (int j = 0; j < 8; j++) acc[i][j] = 0.f;

    for (int k0 = 0; k0 < Kdim; k0 += 16) {
        #pragma unroll
        for (int s = 0; s < 2; s++) {
            int slot = tid + s * 256;           // 0..511
            int r  = slot >> 2;                 // 0..127
            int kq = (slot & 3) * 4;            // 0,4,8,12
            float4 a4 = *(const float4*)(A + (size_t)(bm + r) * Kdim + k0 + kq);
            As[kq + 0][r] = a4.x; As[kq + 1][r] = a4.y;
            As[kq + 2][r] = a4.z; As[kq + 3][r] = a4.w;
            if (TRANSB) {
                float4 b4 = *(const float4*)(B + (size_t)(bn + r) * Kdim + k0 + kq);
                Bs[kq + 0][r] = b4.x; Bs[kq + 1][r] = b4.y;
                Bs[kq + 2][r] = b4.z; Bs[kq + 3][r] = b4.w;
            } else {
                int kk = slot >> 5;             // 0..15
                int c4 = (slot & 31) * 4;       // 0..124
                float4 b4 = *(const float4*)(B + (size_t)(k0 + kk) * Ndim + bn + c4);
                *(float4*)&Bs[kk][c4] = b4;
            }
        }
        __syncthreads();
        #pragma unroll
        for (int kk = 0; kk < 16; kk++) {
            float ra[8], rb[8];
            *(float4*)&ra[0] = *(const float4*)&As[kk][ty * 8];
            *(float4*)&ra[4] = *(const float4*)&As[kk][ty * 8 + 4];
            *(float4*)&rb[0] = *(const float4*)&Bs[kk][tx * 8];
            *(float4*)&rb[4] = *(const float4*)&Bs[kk][tx * 8 + 4];
            #pragma unroll
            for (int i = 0; i < 8; i++)
                #pragma unroll
                for (int j = 0; j < 8; j++)
                    acc[i][j] += ra[i] * rb[j];
        }
        __syncthreads();
    }

    #pragma unroll
    for (int i = 0; i < 8; i++) {
        int row = bm + ty * 8 + i;
        #pragma unroll
        for (int j = 0; j < 8; j += 4) {
            int col = bn + tx * 8 + j;
            size_t off = (size_t)row * Ndim + col;
            float4 o;
            o.x = alpha * acc[i][j + 0];
            o.y = alpha * acc[i][j + 1];
            o.z = alpha * acc[i][j + 2];
            o.w = alpha * acc[i][j + 3];
            if (beta != 0.f) {
                float4 d4 = *(const float4*)(D + off);
                o.x += beta * d4.x; o.y += beta * d4.y;
                o.z += beta * d4.z; o.w += beta * d4.w;
            }
            if (BIAS) {
                float4 b4 = *(const float4*)(bias + col);
                o.x += b4.x; o.y += b4.y; o.z += b4.z; o.w += b4.w;
            }
            *(float4*)(C + off) = o;
        }
    }
}

// ---------------- launch ----------------
extern "C" void kernel_launch(void* const* d_in, const int* in_sizes, int n_in,
                              void* d_out, int out_size) {
    const float* x      = (const float*)d_in[0];   // (4,2048,2048)
    const float* weight = (const float*)d_in[1];   // (2048,2048)
    const float* bias   = (const float*)d_in[2];   // (2048,)
    float* out = (float*)d_out;
    const int Mrows = 4 * 2048;                    // 8192

    float *pM, *pX, *pT, *pY;
    cudaGetSymbolAddress((void**)&pM, g_M);
    cudaGetSymbolAddress((void**)&pX, g_X);
    cudaGetSymbolAddress((void**)&pT, g_T);
    cudaGetSymbolAddress((void**)&pY, g_Y);

    // 1. M = I - (w - w^T)
    build_M_kernel<<<dim3(NN / 256, NN), 256>>>(weight);

    // 2. power iteration: sigma_max(A)^2 estimate (A = I - M, A^T = -A)
    init_v_kernel<<<NN / 256, 256>>>();
    for (int it = 0; it < 24; it++) {
        matvec_A_kernel<<<NN, 256>>>(1, 1.0f);          // u = A v
        matvec_A_kernel<<<NN, 256>>>(0, 1.0f / 64.0f);  // v = (1/64) A u
    }
    matvec_A_kernel<<<NN, 256>>>(1, 1.0f);              // u = A v (for Rayleigh)
    dots_and_c_kernel<<<1, 1024>>>();                   // g_s[2] = c

    // 3. X0 = c * M^T
    init_X0_kernel<<<dim3(NN / 32, NN / 32), dim3(32, 8)>>>();

    // 4. Newton-Schulz: X <- X (2I - M X), 10 iterations (residual -> ~1e-7)
    dim3 grid2k(NN / 128, NN / 128);
    float* Xc = pX; float* Xn = pY;
    for (int it = 0; it < 10; it++) {
        gemm_kernel<false, false><<<grid2k, 256>>>(pT, pM, Xc, nullptr, nullptr,
                                                   NN, NN, NN, 1.0f, 0.0f);
        gemm_kernel<false, false><<<grid2k, 256>>>(Xn, Xc, pT, Xc, nullptr,
                                                   NN, NN, NN, -1.0f, 2.0f);
        float* tmp = Xc; Xc = Xn; Xn = tmp;
    }

    // 5. W = X (2I - M) = 2X - X M   (since I + A = 2I - M)  -> stored in g_T
    gemm_kernel<false, false><<<grid2k, 256>>>(pT, Xc, pM, Xc, nullptr,
                                               NN, NN, NN, -1.0f, 2.0f);

    // 6. out = x @ W^T + bias  (NT GEMM)
    dim3 gridOut(NN / 128, Mrows / 128);
    gemm_kernel<true, true><<<gridOut, 256>>>(out, x, pT, nullptr, bias,
                                              Mrows, NN, NN, 1.0f, 0.0f);
}

// round 3
// speedup vs baseline: 3.9478x; 3.9478x over previous
#include <cuda_runtime.h>
#include <cuda_bf16.h>
#include <cstdint>

#define NN 2048
#define NELEM (NN*NN)
#define K3 (3*NN)
#define MBIG 8192

// ---------------- device scratch ----------------
__device__ float g_M[NELEM];
__device__ float g_X[NELEM];
__device__ float g_Y[NELEM];
__device__ float g_T[NELEM];
__device__ __nv_bfloat16 g_Mbf[NELEM];
__device__ __nv_bfloat16 g_Msp[(size_t)NN*K3];
__device__ __nv_bfloat16 g_Aop[(size_t)MBIG*K3];
__device__ __nv_bfloat16 g_Bop[(size_t)NN*K3];
__device__ float g_v[NN];
__device__ float g_u[NN];
__device__ float g_s[4];

__device__ __forceinline__ uint32_t smem_u32(const void* p) {
    uint32_t a;
    asm("{ .reg .u64 t; cvta.to.shared.u64 t, %1; cvt.u32.u64 %0, t; }" : "=r"(a) : "l"(p));
    return a;
}

// ---------------- small kernels ----------------
__global__ void build_M_kernel(const float* __restrict__ w) {
    int j = blockIdx.x * blockDim.x + threadIdx.x;
    int i = blockIdx.y;
    float a = w[(size_t)i * NN + j] - w[(size_t)j * NN + i];
    float m = (i == j ? 1.0f : 0.0f) - a;
    g_M[(size_t)i * NN + j] = m;
    g_Mbf[(size_t)i * NN + j] = __float2bfloat16(m);
}

__global__ void init_v_kernel() {
    int i = blockIdx.x * blockDim.x + threadIdx.x;
    unsigned h = (unsigned)i * 2654435761u;
    h ^= h >> 16; h *= 2246822519u; h ^= h >> 13;
    g_v[i] = ((h & 0xFFFFFF) / 16777216.0f) - 0.5f;
}

// out = scale * (in - M@in) = scale * A@in
__global__ void matvec_A_kernel(int dst_is_u, float scale) {
    __shared__ float red[256];
    const float* in  = dst_is_u ? g_v : g_u;
    float*       out = dst_is_u ? g_u : g_v;
    int row = blockIdx.x;
    const __nv_bfloat162* Mrow = (const __nv_bfloat162*)(g_Mbf + (size_t)row * NN);
    float s = 0.f;
    #pragma unroll 4
    for (int j = threadIdx.x; j < NN/2; j += 256) {
        __nv_bfloat162 m2 = Mrow[j];
        s += __bfloat162float(m2.x) * in[2*j] + __bfloat162float(m2.y) * in[2*j+1];
    }
    red[threadIdx.x] = s;
    __syncthreads();
    for (int off = 128; off > 0; off >>= 1) {
        if (threadIdx.x < off) red[threadIdx.x] += red[threadIdx.x + off];
        __syncthreads();
    }
    if (threadIdx.x == 0) out[row] = scale * (in[row] - red[0]);
}

__global__ void dots_and_c_kernel() {
    __shared__ float r0[1024], r1[1024];
    int t = threadIdx.x;
    float a = 0.f, b = 0.f;
    for (int i = t; i < NN; i += 1024) { float vv = g_v[i], uu = g_u[i]; a += vv*vv; b += uu*uu; }
    r0[t] = a; r1[t] = b;
    __syncthreads();
    for (int off = 512; off > 0; off >>= 1) {
        if (t < off) { r0[t] += r0[t+off]; r1[t] += r1[t+off]; }
        __syncthreads();
    }
    if (t == 0) {
        float sigma2 = r1[0] / (r0[0] + 1e-30f);
        g_s[2] = 2.0f / (2.0f + 1.25f * sigma2);
    }
}

__global__ void init_X0_kernel() {   // X0 = c * M^T
    __shared__ float tile[32][33];
    int bx = blockIdx.x * 32, by = blockIdx.y * 32;
    #pragma unroll
    for (int dy = 0; dy < 32; dy += 8)
        tile[threadIdx.y + dy][threadIdx.x] = g_M[(size_t)(by + threadIdx.y + dy) * NN + bx + threadIdx.x];
    __syncthreads();
    float c = g_s[2];
    #pragma unroll
    for (int dy = 0; dy < 32; dy += 8)
        g_X[(size_t)(bx + threadIdx.y + dy) * NN + by + threadIdx.x] = c * tile[threadIdx.x][threadIdx.y + dy];
}

__global__ void form_W_kernel(const float* __restrict__ X, float* __restrict__ W) {
    int t = blockIdx.x * blockDim.x + threadIdx.x;   // W = 2X - I
    int i = t / NN, j = t % NN;
    W[t] = 2.0f * X[t] - (i == j ? 1.0f : 0.0f);
}

__global__ void conv_hi_kernel(const float* __restrict__ src, __nv_bfloat16* __restrict__ dst, int n) {
    int i = (blockIdx.x * blockDim.x + threadIdx.x) * 4;
    if (i >= n) return;
    float4 v = *(const float4*)(src + i);
    __nv_bfloat162 h0, h1;
    h0.x = __float2bfloat16(v.x); h0.y = __float2bfloat16(v.y);
    h1.x = __float2bfloat16(v.z); h1.y = __float2bfloat16(v.w);
    *(__nv_bfloat162*)(dst + i)     = h0;
    *(__nv_bfloat162*)(dst + i + 2) = h1;
}

// transpose + hi: src PxQ fp32 -> dst QxP bf16
__global__ void conv_hi_T_kernel(const float* __restrict__ src, __nv_bfloat16* __restrict__ dst, int P, int Q) {
    __shared__ float tile[32][33];
    int bx = blockIdx.x * 32, by = blockIdx.y * 32;
    #pragma unroll
    for (int dy = 0; dy < 32; dy += 8)
        tile[threadIdx.y + dy][threadIdx.x] = src[(size_t)(by + threadIdx.y + dy) * Q + bx + threadIdx.x];
    __syncthreads();
    #pragma unroll
    for (int dy = 0; dy < 32; dy += 8) {
        int q = bx + threadIdx.y + dy, p = by + threadIdx.x;
        dst[(size_t)q * P + p] = __float2bfloat16(tile[threadIdx.x][threadIdx.y + dy]);
    }
}

// split: src PxQ fp32 -> dst Px(3Q). modeB=0: [hi|lo|hi]; modeB=1: [hi|hi|lo]
__global__ void conv_split_kernel(const float* __restrict__ src, __nv_bfloat16* __restrict__ dst,
                                  int P, int Q, int modeB) {
    int t = blockIdx.x * blockDim.x + threadIdx.x;
    int nq = Q >> 2;
    if (t >= P * nq) return;
    int p = t / nq, q = (t % nq) * 4;
    float4 v = *(const float4*)(src + (size_t)p * Q + q);
    __nv_bfloat162 hi0, hi1, lo0, lo1;
    hi0.x = __float2bfloat16(v.x); lo0.x = __float2bfloat16(v.x - __bfloat162float(hi0.x));
    hi0.y = __float2bfloat16(v.y); lo0.y = __float2bfloat16(v.y - __bfloat162float(hi0.y));
    hi1.x = __float2bfloat16(v.z); lo1.x = __float2bfloat16(v.z - __bfloat162float(hi1.x));
    hi1.y = __float2bfloat16(v.w); lo1.y = __float2bfloat16(v.w - __bfloat162float(hi1.y));
    size_t ro = (size_t)p * 3 * Q + q;
    *(__nv_bfloat162*)(dst + ro)     = hi0;
    *(__nv_bfloat162*)(dst + ro + 2) = hi1;
    *(__nv_bfloat162*)(dst + ro + Q)     = modeB ? hi0 : lo0;
    *(__nv_bfloat162*)(dst + ro + Q + 2) = modeB ? hi1 : lo1;
    *(__nv_bfloat162*)(dst + ro + 2*Q)     = modeB ? lo0 : hi0;
    *(__nv_bfloat162*)(dst + ro + 2*Q + 2) = modeB ? lo1 : hi1;
}

// transpose + split: src PxQ fp32 -> dst Qx(3P)
__global__ void conv_split_T_kernel(const float* __restrict__ src, __nv_bfloat16* __restrict__ dst,
                                    int P, int Q, int modeB) {
    __shared__ float tile[32][33];
    int bx = blockIdx.x * 32, by = blockIdx.y * 32;
    #pragma unroll
    for (int dy = 0; dy < 32; dy += 8)
        tile[threadIdx.y + dy][threadIdx.x] = src[(size_t)(by + threadIdx.y + dy) * Q + bx + threadIdx.x];
    __syncthreads();
    #pragma unroll
    for (int dy = 0; dy < 32; dy += 8) {
        int q = bx + threadIdx.y + dy, p = by + threadIdx.x;
        float v = tile[threadIdx.x][threadIdx.y + dy];
        __nv_bfloat16 hi = __float2bfloat16(v);
        __nv_bfloat16 lo = __float2bfloat16(v - __bfloat162float(hi));
        size_t ro = (size_t)q * 3 * P;
        dst[ro + p]       = hi;
        dst[ro + P + p]   = modeB ? hi : lo;
        dst[ro + 2*P + p] = modeB ? lo : hi;
    }
}

// ---------------- mma.sync bf16 GEMM ----------------
// C[m][n] = alpha * sum_k A[m][k]*B[n][k] + beta*Dext + bias
// A: Mdim x Kdim bf16 K-major; B: Ndim x Kdim bf16 K-major. Kdim % 32 == 0.
// BM=BN=128, BK=32, 256 threads, 8 warps (2x4), warp tile 64x32, 3-stage cp.async.
#define SK 40            // padded smem stride (elems); 80B rows -> conflict-free ldmatrix
#define TILE_B (128*SK*2)
#define NSTAGE 3

__global__ void __launch_bounds__(256, 2) mma_gemm_kernel(
    float* __restrict__ C, const __nv_bfloat16* __restrict__ A,
    const __nv_bfloat16* __restrict__ B, const float* __restrict__ Dext,
    const float* __restrict__ bias, int Ndim, int Kdim, float alpha, float beta)
{
    __shared__ __align__(16) char smem[NSTAGE * 2 * TILE_B];
    uint32_t sbase = smem_u32(smem);
    int tid = threadIdx.x;
    int wid = tid >> 5, lid = tid & 31;
    int warp_m = wid >> 2, warp_n = wid & 3;       // 2 x 4
    int bm = blockIdx.y * 128, bn = blockIdx.x * 128;

    float acc[4][4][4];
    #pragma unroll
    for (int i = 0; i < 4; i++)
        #pragma unroll
        for (int j = 0; j < 4; j++)
            #pragma unroll
            for (int r = 0; r < 4; r++) acc[i][j][r] = 0.f;

    // per-thread load slots: 2 chunks A + 2 chunks B per stage
    int arow[2], aoff[2];
    #pragma unroll
    for (int s = 0; s < 2; s++) {
        int c = tid + s * 256;       // 0..511
        arow[s] = c >> 2;            // 0..127
        aoff[s] = c & 3;             // 16B chunk
    }

    auto load_stage = [&](int stage, int kt) {
        uint32_t sA = sbase + stage * 2 * TILE_B;
        uint32_t sB = sA + TILE_B;
        #pragma unroll
        for (int s = 0; s < 2; s++) {
            const char* gA = (const char*)(A + (size_t)(bm + arow[s]) * Kdim + kt + aoff[s] * 8);
            uint32_t dA = sA + arow[s] * (SK*2) + aoff[s] * 16;
            asm volatile("cp.async.cg.shared.global [%0], [%1], 16;" :: "r"(dA), "l"(gA));
            const char* gB = (const char*)(B + (size_t)(bn + arow[s]) * Kdim + kt + aoff[s] * 8);
            uint32_t dB = sB + arow[s] * (SK*2) + aoff[s] * 16;
            asm volatile("cp.async.cg.shared.global [%0], [%1], 16;" :: "r"(dB), "l"(gB));
        }
        asm volatile("cp.async.commit_group;" ::: "memory");
    };

    const int NB = Kdim >> 5;
    load_stage(0, 0);
    load_stage(1, 32);

    // ldmatrix lane addressing (within-tile byte offsets)
    uint32_t a_lane_off = (uint32_t)((lid & 15) * (SK*2) + ((lid >> 4) & 1) * 16);
    uint32_t b_lane_off = (uint32_t)((((lid & 7) + ((lid >> 4) & 1) * 8) * (SK*2)) + (((lid >> 3) & 1) * 16));

    for (int kb = 0; kb < NB; kb++) {
        if (kb >= NB - 2) asm volatile("cp.async.wait_group 0;" ::: "memory");
        else              asm volatile("cp.async.wait_group %0;" :: "n"(NSTAGE - 2) : "memory");
        __syncthreads();

        int stage = kb % NSTAGE;
        uint32_t sA = sbase + stage * 2 * TILE_B + warp_m * 64 * (SK*2);
        uint32_t sB = sbase + stage * 2 * TILE_B + TILE_B + warp_n * 32 * (SK*2);

        #pragma unroll
        for (int kk = 0; kk < 2; kk++) {           // two k16 steps
            uint32_t af[4][4], bf[2][4];
            #pragma unroll
            for (int mi = 0; mi < 4; mi++) {
                uint32_t addr = sA + mi * 16 * (SK*2) + kk * 32 + a_lane_off;
                asm volatile("ldmatrix.sync.aligned.m8n8.x4.shared.b16 {%0,%1,%2,%3}, [%4];"
                    : "=r"(af[mi][0]), "=r"(af[mi][1]), "=r"(af[mi][2]), "=r"(af[mi][3]) : "r"(addr));
            }
            #pragma unroll
            for (int nj = 0; nj < 2; nj++) {
                uint32_t addr = sB + nj * 16 * (SK*2) + kk * 32 + b_lane_off;
                asm volatile("ldmatrix.sync.aligned.m8n8.x4.shared.b16 {%0,%1,%2,%3}, [%4];"
                    : "=r"(bf[nj][0]), "=r"(bf[nj][1]), "=r"(bf[nj][2]), "=r"(bf[nj][3]) : "r"(addr));
            }
            #pragma unroll
            for (int mi = 0; mi < 4; mi++) {
                #pragma unroll
                for (int nj = 0; nj < 4; nj++) {
                    uint32_t b0 = bf[nj >> 1][(nj & 1) ? 2 : 0];
                    uint32_t b1 = bf[nj >> 1][(nj & 1) ? 3 : 1];
                    asm volatile(
                        "mma.sync.aligned.m16n8k16.row.col.f32.bf16.bf16.f32 "
                        "{%0,%1,%2,%3}, {%4,%5,%6,%7}, {%8,%9}, {%0,%1,%2,%3};"
                        : "+f"(acc[mi][nj][0]), "+f"(acc[mi][nj][1]),
                          "+f"(acc[mi][nj][2]), "+f"(acc[mi][nj][3])
                        : "r"(af[mi][0]), "r"(af[mi][1]), "r"(af[mi][2]), "r"(af[mi][3]),
                          "r"(b0), "r"(b1));
                }
            }
        }
        __syncthreads();
        if (kb + 2 < NB) load_stage((kb + 2) % NSTAGE, (kb + 2) * 32);
    }

    // epilogue: lane row groups
    int lrow = lid >> 2, lcol = (lid & 3) * 2;
    #pragma unroll
    for (int mi = 0; mi < 4; mi++) {
        #pragma unroll
        for (int half = 0; half < 2; half++) {
            int row = bm + warp_m * 64 + mi * 16 + lrow + half * 8;
            #pragma unroll
            for (int nj = 0; nj < 4; nj++) {
                int col = bn + warp_n * 32 + nj * 8 + lcol;
                size_t off = (size_t)row * Ndim + col;
                float2 o;
                o.x = alpha * acc[mi][nj][half * 2 + 0];
                o.y = alpha * acc[mi][nj][half * 2 + 1];
                if (Dext) {
                    float2 d2 = *(const float2*)(Dext + off);
                    o.x += beta * d2.x; o.y += beta * d2.y;
                }
                if (bias) {
                    float2 b2 = *(const float2*)(bias + col);
                    o.x += b2.x; o.y += b2.y;
                }
                *(float2*)(C + off) = o;
            }
        }
    }
}

// ---------------- launch ----------------
extern "C" void kernel_launch(void* const* d_in, const int* in_sizes, int n_in,
                              void* d_out, int out_size) {
    const float* x      = (const float*)d_in[0];
    const float* weight = (const float*)d_in[1];
    const float* bias   = (const float*)d_in[2];
    float* out = (float*)d_out;

    float *pM, *pX, *pY, *pT;
    __nv_bfloat16 *pMbf, *pMsp, *pAop, *pBop;
    cudaGetSymbolAddress((void**)&pM, g_M);
    cudaGetSymbolAddress((void**)&pX, g_X);
    cudaGetSymbolAddress((void**)&pY, g_Y);
    cudaGetSymbolAddress((void**)&pT, g_T);
    cudaGetSymbolAddress((void**)&pMbf, g_Mbf);
    cudaGetSymbolAddress((void**)&pMsp, g_Msp);
    cudaGetSymbolAddress((void**)&pAop, g_Aop);
    cudaGetSymbolAddress((void**)&pBop, g_Bop);

    // 1. M = I - (w - w^T) (fp32 + bf16)
    build_M_kernel<<<dim3(NN/256, NN), 256>>>(weight);

    // 2. power iteration for sigma^2, then c
    init_v_kernel<<<NN/256, 256>>>();
    for (int it = 0; it < 12; it++) {
        matvec_A_kernel<<<NN, 256>>>(1, 1.0f);
        matvec_A_kernel<<<NN, 256>>>(0, 1.0f / 64.0f);
    }
    matvec_A_kernel<<<NN, 256>>>(1, 1.0f);
    dots_and_c_kernel<<<1, 1024>>>();

    // 3. X0 = c * M^T
    init_X0_kernel<<<dim3(NN/32, NN/32), dim3(32, 8)>>>();

    dim3 g2k(NN/128, NN/128);
    dim3 tgrid(NN/32, NN/32), tblk(32, 8);
    float* Xc = pX; float* Xn = pY;

    // 4a. Newton in bf16: X <- X(2I - MX), 8 iters
    for (int it = 0; it < 8; it++) {
        conv_hi_T_kernel<<<tgrid, tblk>>>(Xc, pBop, NN, NN);                 // B = X^T
        mma_gemm_kernel<<<g2k, 256>>>(pT, pMbf, pBop, nullptr, nullptr,
                                      NN, NN, 1.0f, 0.0f);                   // T = M X
        conv_hi_kernel<<<NELEM/4/256, 256>>>(Xc, pAop, NELEM);               // A = X
        conv_hi_T_kernel<<<tgrid, tblk>>>(pT, pBop, NN, NN);                 // B = T^T
        mma_gemm_kernel<<<g2k, 256>>>(Xn, pAop, pBop, Xc, nullptr,
                                      NN, NN, -1.0f, 2.0f);                  // Y = 2X - X T
        float* t = Xc; Xc = Xn; Xn = t;
    }

    // 4b. Newton polish with split-bf16 (K'=6144), 2 iters
    conv_split_kernel<<<NELEM/4/256, 256>>>(pM, pMsp, NN, NN, 0);
    for (int it = 0; it < 2; it++) {
        conv_split_T_kernel<<<tgrid, tblk>>>(Xc, pBop, NN, NN, 1);
        mma_gemm_kernel<<<g2k, 256>>>(pT, pMsp, pBop, nullptr, nullptr,
                                      NN, K3, 1.0f, 0.0f);
        conv_split_kernel<<<NELEM/4/256, 256>>>(Xc, pAop, NN, NN, 0);
        conv_split_T_kernel<<<tgrid, tblk>>>(pT, pBop, NN, NN, 1);
        mma_gemm_kernel<<<g2k, 256>>>(Xn, pAop, pBop, Xc, nullptr,
                                      NN, K3, -1.0f, 2.0f);
        float* t = Xc; Xc = Xn; Xn = t;
    }

    // 5. W = 2X - I (elementwise)
    form_W_kernel<<<NELEM/256, 256>>>(Xc, pT);

    // 6. out = x W^T + bias (split-bf16, K'=6144)
    conv_split_kernel<<<(MBIG*NN/4)/256, 256>>>(x, pAop, MBIG, NN, 0);
    conv_split_kernel<<<NELEM/4/256, 256>>>(pT, pBop, NN, NN, 1);
    mma_gemm_kernel<<<dim3(NN/128, MBIG/128), 256>>>(out, pAop, pBop, nullptr, bias,
                                                     NN, K3, 1.0f, 0.0f);
}

// round 4
// speedup vs baseline: 5.0812x; 1.2871x over previous
#include <cuda_runtime.h>
#include <cuda_bf16.h>
#include <cstdint>

#define NN 2048
#define NELEM (NN*NN)
#define K3 (3*NN)
#define MBIG 8192

// ---------------- device scratch ----------------
__device__ float g_X[NELEM];
__device__ float g_Y[NELEM];
__device__ float g_M[NELEM];
__device__ __nv_bfloat16 g_Mbf[NELEM];
__device__ __nv_bfloat16 g_Tbf[NELEM];
__device__ __nv_bfloat16 g_Xbf0[NELEM];
__device__ __nv_bfloat16 g_Xbf1[NELEM];
__device__ __nv_bfloat16 g_Msp[(size_t)NN*K3];    // M split [hi|lo|hi] along k (A-op)
__device__ __nv_bfloat16 g_XspR[(size_t)K3*NN];   // X split rows [hi;hi;lo] (B-op, trans)
__device__ __nv_bfloat16 g_xsp[(size_t)MBIG*K3];  // x split [hi|lo|hi]
__device__ __nv_bfloat16 g_Wsp[(size_t)NN*K3];    // W split [hi|hi|lo]
__device__ float g_v[NN];
__device__ float g_u[NN];
__device__ float g_s[4];

__device__ __forceinline__ uint32_t smem_u32(const void* p) {
    uint32_t a;
    asm("{ .reg .u64 t; cvta.to.shared.u64 t, %1; cvt.u32.u64 %0, t; }" : "=r"(a) : "l"(p));
    return a;
}

// ---------------- small kernels ----------------
__global__ void build_M_kernel(const float* __restrict__ w) {
    int j = blockIdx.x * blockDim.x + threadIdx.x;
    int i = blockIdx.y;
    float a = w[(size_t)i * NN + j] - w[(size_t)j * NN + i];
    float m = (i == j ? 1.0f : 0.0f) - a;
    g_M[(size_t)i * NN + j] = m;
    g_Mbf[(size_t)i * NN + j] = __float2bfloat16(m);
}

__global__ void init_v_kernel() {
    int i = blockIdx.x * blockDim.x + threadIdx.x;
    unsigned h = (unsigned)i * 2654435761u;
    h ^= h >> 16; h *= 2246822519u; h ^= h >> 13;
    g_v[i] = ((h & 0xFFFFFF) / 16777216.0f) - 0.5f;
}

// out = scale * (in - M@in) = scale * A@in
__global__ void matvec_A_kernel(int dst_is_u, float scale) {
    __shared__ float red[256];
    const float* in  = dst_is_u ? g_v : g_u;
    float*       out = dst_is_u ? g_u : g_v;
    int row = blockIdx.x;
    const __nv_bfloat162* Mrow = (const __nv_bfloat162*)(g_Mbf + (size_t)row * NN);
    float s = 0.f;
    #pragma unroll 4
    for (int j = threadIdx.x; j < NN/2; j += 256) {
        __nv_bfloat162 m2 = Mrow[j];
        s += __bfloat162float(m2.x) * in[2*j] + __bfloat162float(m2.y) * in[2*j+1];
    }
    red[threadIdx.x] = s;
    __syncthreads();
    for (int off = 128; off > 0; off >>= 1) {
        if (threadIdx.x < off) red[threadIdx.x] += red[threadIdx.x + off];
        __syncthreads();
    }
    if (threadIdx.x == 0) out[row] = scale * (in[row] - red[0]);
}

__global__ void dots_and_c_kernel() {
    __shared__ float r0[1024], r1[1024];
    int t = threadIdx.x;
    float a = 0.f, b = 0.f;
    for (int i = t; i < NN; i += 1024) { float vv = g_v[i], uu = g_u[i]; a += vv*vv; b += uu*uu; }
    r0[t] = a; r1[t] = b;
    __syncthreads();
    for (int off = 512; off > 0; off >>= 1) {
        if (t < off) { r0[t] += r0[t+off]; r1[t] += r1[t+off]; }
        __syncthreads();
    }
    if (t == 0) {
        float sigma2 = r1[0] / (r0[0] + 1e-30f);
        g_s[2] = 2.0f / (2.0f + 1.25f * sigma2);
    }
}

__global__ void init_X0_kernel() {   // X0 = c * M^T  (fp32 + bf16)
    __shared__ float tile[32][33];
    int bx = blockIdx.x * 32, by = blockIdx.y * 32;
    #pragma unroll
    for (int dy = 0; dy < 32; dy += 8)
        tile[threadIdx.y + dy][threadIdx.x] = g_M[(size_t)(by + threadIdx.y + dy) * NN + bx + threadIdx.x];
    __syncthreads();
    float c = g_s[2];
    #pragma unroll
    for (int dy = 0; dy < 32; dy += 8) {
        float v = c * tile[threadIdx.x][threadIdx.y + dy];
        size_t off = (size_t)(bx + threadIdx.y + dy) * NN + by + threadIdx.x;
        g_X[off] = v;
        g_Xbf0[off] = __float2bfloat16(v);
    }
}

// split: src PxQ fp32 -> dst Px(3Q). [hi|lo|hi] along columns (A-op convention)
__global__ void conv_splitA_kernel(const float* __restrict__ src, __nv_bfloat16* __restrict__ dst,
                                   int P, int Q) {
    int t = blockIdx.x * blockDim.x + threadIdx.x;
    int nq = Q >> 2;
    if (t >= P * nq) return;
    int p = t / nq, q = (t % nq) * 4;
    float4 v = *(const float4*)(src + (size_t)p * Q + q);
    __nv_bfloat162 hi0, hi1, lo0, lo1;
    hi0.x = __float2bfloat16(v.x); lo0.x = __float2bfloat16(v.x - __bfloat162float(hi0.x));
    hi0.y = __float2bfloat16(v.y); lo0.y = __float2bfloat16(v.y - __bfloat162float(hi0.y));
    hi1.x = __float2bfloat16(v.z); lo1.x = __float2bfloat16(v.z - __bfloat162float(hi1.x));
    hi1.y = __float2bfloat16(v.w); lo1.y = __float2bfloat16(v.w - __bfloat162float(hi1.y));
    size_t ro = (size_t)p * 3 * Q + q;
    *(__nv_bfloat162*)(dst + ro)         = hi0;
    *(__nv_bfloat162*)(dst + ro + 2)     = hi1;
    *(__nv_bfloat162*)(dst + ro + Q)     = lo0;
    *(__nv_bfloat162*)(dst + ro + Q + 2) = lo1;
    *(__nv_bfloat162*)(dst + ro + 2*Q)     = hi0;
    *(__nv_bfloat162*)(dst + ro + 2*Q + 2) = hi1;
}

// X fp32 (NNxNN) -> XspR rows [hi; hi; lo]  (B-op for trans path, split along k-rows)
__global__ void xsp_rows_kernel(const float* __restrict__ X) {
    int t = blockIdx.x * blockDim.x + threadIdx.x;
    int row = t >> 9, q = (t & 511) * 4;       // 2048/4 = 512 float4 per row
    float4 v = *(const float4*)(X + (size_t)row * NN + q);
    __nv_bfloat162 hi0, hi1, lo0, lo1;
    hi0.x = __float2bfloat16(v.x); lo0.x = __float2bfloat16(v.x - __bfloat162float(hi0.x));
    hi0.y = __float2bfloat16(v.y); lo0.y = __float2bfloat16(v.y - __bfloat162float(hi0.y));
    hi1.x = __float2bfloat16(v.z); lo1.x = __float2bfloat16(v.z - __bfloat162float(hi1.x));
    hi1.y = __float2bfloat16(v.w); lo1.y = __float2bfloat16(v.w - __bfloat162float(hi1.y));
    size_t r0 = (size_t)row * NN + q;
    size_t r1 = (size_t)(NN + row) * NN + q;
    size_t r2 = (size_t)(2*NN + row) * NN + q;
    *(__nv_bfloat162*)(g_XspR + r0) = hi0; *(__nv_bfloat162*)(g_XspR + r0 + 2) = hi1;
    *(__nv_bfloat162*)(g_XspR + r1) = hi0; *(__nv_bfloat162*)(g_XspR + r1 + 2) = hi1;
    *(__nv_bfloat162*)(g_XspR + r2) = lo0; *(__nv_bfloat162*)(g_XspR + r2 + 2) = lo1;
}

// W = 2X - I, split [hi|hi|lo] along columns into g_Wsp
__global__ void conv_W_split_kernel(const float* __restrict__ X) {
    int t = blockIdx.x * blockDim.x + threadIdx.x;
    int o = t >> 9, i = (t & 511) * 4;
    float4 v = *(const float4*)(X + (size_t)o * NN + i);
    float w0 = 2.f*v.x - (o == i+0 ? 1.f : 0.f);
    float w1 = 2.f*v.y - (o == i+1 ? 1.f : 0.f);
    float w2 = 2.f*v.z - (o == i+2 ? 1.f : 0.f);
    float w3 = 2.f*v.w - (o == i+3 ? 1.f : 0.f);
    __nv_bfloat162 hi0, hi1, lo0, lo1;
    hi0.x = __float2bfloat16(w0); lo0.x = __float2bfloat16(w0 - __bfloat162float(hi0.x));
    hi0.y = __float2bfloat16(w1); lo0.y = __float2bfloat16(w1 - __bfloat162float(hi0.y));
    hi1.x = __float2bfloat16(w2); lo1.x = __float2bfloat16(w2 - __bfloat162float(hi1.x));
    hi1.y = __float2bfloat16(w3); lo1.y = __float2bfloat16(w3 - __bfloat162float(hi1.y));
    size_t ro = (size_t)o * K3 + i;
    *(__nv_bfloat162*)(g_Wsp + ro)          = hi0;
    *(__nv_bfloat162*)(g_Wsp + ro + 2)      = hi1;
    *(__nv_bfloat162*)(g_Wsp + ro + NN)     = hi0;
    *(__nv_bfloat162*)(g_Wsp + ro + NN + 2) = hi1;
    *(__nv_bfloat162*)(g_Wsp + ro + 2*NN)     = lo0;
    *(__nv_bfloat162*)(g_Wsp + ro + 2*NN + 2) = lo1;
}

// ---------------- mma.sync bf16 GEMM ----------------
// acc[m][n] = sum_k A[m][k]*B'[k][n]
//   BMODE 0: B is K-major (B[n][k], Ndim rows x Kdim cols), non-trans ldmatrix
//   BMODE 1: B is row-major (B[k][n], Kdim rows x Ndim cols), trans ldmatrix
// out = alpha*acc + beta*Dext + bias + addI; written to outF (fp32) and/or outB (bf16).
#define SK 40
#define ASZ (128*SK*2)      // 10240
#define BSZ 10240
#define BT_STRIDE 272       // trans B tile row stride (bytes): 136 bf16
#define NSTAGE 3

template<int BMODE>
__global__ void __launch_bounds__(256, 2) mma_gemm_kernel(
    float* outF, __nv_bfloat16* outB,
    const __nv_bfloat16* __restrict__ A, const __nv_bfloat16* __restrict__ B,
    const float* __restrict__ Dext, const float* __restrict__ bias,
    int Ndim, int Kdim, float alpha, float beta, int addI)
{
    __shared__ __align__(16) char smem[NSTAGE * (ASZ + BSZ)];
    uint32_t sbase = smem_u32(smem);
    int tid = threadIdx.x;
    int wid = tid >> 5, lid = tid & 31;
    int warp_m = wid >> 2, warp_n = wid & 3;
    int bm = blockIdx.y * 128, bn = blockIdx.x * 128;

    float acc[4][4][4];
    #pragma unroll
    for (int i = 0; i < 4; i++)
        #pragma unroll
        for (int j = 0; j < 4; j++)
            #pragma unroll
            for (int r = 0; r < 4; r++) acc[i][j][r] = 0.f;

    auto load_stage = [&](int stage, int kt) {
        uint32_t sA = sbase + stage * (ASZ + BSZ);
        uint32_t sB = sA + ASZ;
        #pragma unroll
        for (int s = 0; s < 2; s++) {
            int c = tid + s * 256;
            int row = c >> 2, kc = c & 3;
            const char* gA = (const char*)(A + (size_t)(bm + row) * Kdim + kt + kc * 8);
            uint32_t dA = sA + row * (SK*2) + kc * 16;
            asm volatile("cp.async.cg.shared.global [%0], [%1], 16;" :: "r"(dA), "l"(gA));
            if (BMODE == 0) {
                const char* gB = (const char*)(B + (size_t)(bn + row) * Kdim + kt + kc * 8);
                uint32_t dB = sB + row * (SK*2) + kc * 16;
                asm volatile("cp.async.cg.shared.global [%0], [%1], 16;" :: "r"(dB), "l"(gB));
            } else {
                int r = c >> 4, nch = c & 15;
                const char* gB = (const char*)(B + (size_t)(kt + r) * Ndim + bn + nch * 8);
                uint32_t dB = sB + r * BT_STRIDE + nch * 16;
                asm volatile("cp.async.cg.shared.global [%0], [%1], 16;" :: "r"(dB), "l"(gB));
            }
        }
        asm volatile("cp.async.commit_group;" ::: "memory");
    };

    const int NB = Kdim >> 5;
    load_stage(0, 0);
    load_stage(1, 32);

    uint32_t a_lane_off = (uint32_t)((lid & 15) * (SK*2) + ((lid >> 4) & 1) * 16);
    uint32_t b_lane_off0 = (uint32_t)((((lid & 7) + ((lid >> 4) & 1) * 8) * (SK*2)) + (((lid >> 3) & 1) * 16));
    // trans path lane parts
    int bg = lid >> 3, bw = lid & 7;
    uint32_t bt_krow = (uint32_t)((bg & 1) * 8 + bw);       // k within 16
    uint32_t bt_ncol = (uint32_t)((bg >> 1) * 8);           // n within 16

    for (int kb = 0; kb < NB; kb++) {
        if (kb >= NB - 2) asm volatile("cp.async.wait_group 0;" ::: "memory");
        else              asm volatile("cp.async.wait_group %0;" :: "n"(NSTAGE - 2) : "memory");
        __syncthreads();

        int stage = kb % NSTAGE;
        uint32_t sA = sbase + stage * (ASZ + BSZ) + warp_m * 64 * (SK*2);
        uint32_t sBb = sbase + stage * (ASZ + BSZ) + ASZ;

        #pragma unroll
        for (int kk = 0; kk < 2; kk++) {
            uint32_t af[4][4], bf[2][4];
            #pragma unroll
            for (int mi = 0; mi < 4; mi++) {
                uint32_t addr = sA + mi * 16 * (SK*2) + kk * 32 + a_lane_off;
                asm volatile("ldmatrix.sync.aligned.m8n8.x4.shared.b16 {%0,%1,%2,%3}, [%4];"
                    : "=r"(af[mi][0]), "=r"(af[mi][1]), "=r"(af[mi][2]), "=r"(af[mi][3]) : "r"(addr));
            }
            #pragma unroll
            for (int nj = 0; nj < 2; nj++) {
                if (BMODE == 0) {
                    uint32_t addr = sBb + (warp_n * 32 + nj * 16) * (SK*2) + kk * 32 + b_lane_off0;
                    asm volatile("ldmatrix.sync.aligned.m8n8.x4.shared.b16 {%0,%1,%2,%3}, [%4];"
                        : "=r"(bf[nj][0]), "=r"(bf[nj][1]), "=r"(bf[nj][2]), "=r"(bf[nj][3]) : "r"(addr));
                } else {
                    uint32_t addr = sBb + (kk * 16 + bt_krow) * BT_STRIDE
                                  + (warp_n * 32 + nj * 16 + bt_ncol) * 2;
                    asm volatile("ldmatrix.sync.aligned.m8n8.x4.trans.shared.b16 {%0,%1,%2,%3}, [%4];"
                        : "=r"(bf[nj][0]), "=r"(bf[nj][1]), "=r"(bf[nj][2]), "=r"(bf[nj][3]) : "r"(addr));
                }
            }
            #pragma unroll
            for (int mi = 0; mi < 4; mi++) {
                #pragma unroll
                for (int nj = 0; nj < 4; nj++) {
                    uint32_t b0 = bf[nj >> 1][(nj & 1) ? 2 : 0];
                    uint32_t b1 = bf[nj >> 1][(nj & 1) ? 3 : 1];
                    asm volatile(
                        "mma.sync.aligned.m16n8k16.row.col.f32.bf16.bf16.f32 "
                        "{%0,%1,%2,%3}, {%4,%5,%6,%7}, {%8,%9}, {%0,%1,%2,%3};"
                        : "+f"(acc[mi][nj][0]), "+f"(acc[mi][nj][1]),
                          "+f"(acc[mi][nj][2]), "+f"(acc[mi][nj][3])
                        : "r"(af[mi][0]), "r"(af[mi][1]), "r"(af[mi][2]), "r"(af[mi][3]),
                          "r"(b0), "r"(b1));
                }
            }
        }
        __syncthreads();
        if (kb + 2 < NB) load_stage((kb + 2) % NSTAGE, (kb + 2) * 32);
    }

    int lrow = lid >> 2, lcol = (lid & 3) * 2;
    #pragma unroll
    for (int mi = 0; mi < 4; mi++) {
        #pragma unroll
        for (int half = 0; half < 2; half++) {
            int row = bm + warp_m * 64 + mi * 16 + lrow + half * 8;
            #pragma unroll
            for (int nj = 0; nj < 4; nj++) {
                int col = bn + warp_n * 32 + nj * 8 + lcol;
                size_t off = (size_t)row * Ndim + col;
                float2 o;
                o.x = alpha * acc[mi][nj][half * 2 + 0];
                o.y = alpha * acc[mi][nj][half * 2 + 1];
                if (Dext) {
                    float2 d2 = *(const float2*)(Dext + off);
                    o.x += beta * d2.x; o.y += beta * d2.y;
                }
                if (bias) {
                    float2 b2 = *(const float2*)(bias + col);
                    o.x += b2.x; o.y += b2.y;
                }
                if (addI) {
                    if (row == col)     o.x += 1.f;
                    if (row == col + 1) o.y += 1.f;
                }
                if (outF) *(float2*)(outF + off) = o;
                if (outB) {
                    __nv_bfloat162 h;
                    h.x = __float2bfloat16(o.x); h.y = __float2bfloat16(o.y);
                    *(__nv_bfloat162*)(outB + off) = h;
                }
            }
        }
    }
}

// ---------------- launch ----------------
extern "C" void kernel_launch(void* const* d_in, const int* in_sizes, int n_in,
                              void* d_out, int out_size) {
    const float* x      = (const float*)d_in[0];
    const float* weight = (const float*)d_in[1];
    const float* bias   = (const float*)d_in[2];
    float* out = (float*)d_out;

    float *pX, *pY, *pM;
    __nv_bfloat16 *pMbf, *pTbf, *pXbf0, *pXbf1, *pMsp, *pXspR, *pxsp, *pWsp;
    cudaGetSymbolAddress((void**)&pX, g_X);
    cudaGetSymbolAddress((void**)&pY, g_Y);
    cudaGetSymbolAddress((void**)&pM, g_M);
    cudaGetSymbolAddress((void**)&pMbf, g_Mbf);
    cudaGetSymbolAddress((void**)&pTbf, g_Tbf);
    cudaGetSymbolAddress((void**)&pXbf0, g_Xbf0);
    cudaGetSymbolAddress((void**)&pXbf1, g_Xbf1);
    cudaGetSymbolAddress((void**)&pMsp, g_Msp);
    cudaGetSymbolAddress((void**)&pXspR, g_XspR);
    cudaGetSymbolAddress((void**)&pxsp, g_xsp);
    cudaGetSymbolAddress((void**)&pWsp, g_Wsp);

    // 1. M = I - (w - w^T)
    build_M_kernel<<<dim3(NN/256, NN), 256>>>(weight);

    // 2. power iteration for sigma^2 -> c
    init_v_kernel<<<NN/256, 256>>>();
    for (int it = 0; it < 8; it++) {
        matvec_A_kernel<<<NN, 256>>>(1, 1.0f);
        matvec_A_kernel<<<NN, 256>>>(0, 1.0f / 64.0f);
    }
    matvec_A_kernel<<<NN, 256>>>(1, 1.0f);
    dots_and_c_kernel<<<1, 1024>>>();

    // 3. X0 = c * M^T (fp32 + bf16)
    init_X0_kernel<<<dim3(NN/32, NN/32), dim3(32, 8)>>>();

    // M split for polish (can run any time before polish)
    conv_splitA_kernel<<<(NELEM/4)/256, 256>>>(pM, pMsp, NN, NN);

    dim3 g2k(NN/128, NN/128);
    float *Xf = pX, *Xfn = pY;
    __nv_bfloat16 *Xb = pXbf0, *Xbn = pXbf1;

    // 4a. Newton bf16: 7 iters, 2 GEMMs each, zero conversions
    for (int it = 0; it < 7; it++) {
        // T = M * X   (B = Xb row-major, trans path; bf16 output only)
        mma_gemm_kernel<1><<<g2k, 256>>>(nullptr, pTbf, pMbf, Xb, nullptr, nullptr,
                                         NN, NN, 1.0f, 0.0f, 0);
        // Xn = 2*X - Xb*T   (fp32 + bf16 outputs)
        mma_gemm_kernel<1><<<g2k, 256>>>(Xfn, Xbn, Xb, pTbf, Xf, nullptr,
                                         NN, NN, -1.0f, 2.0f, 0);
        float* tf = Xf; Xf = Xfn; Xfn = tf;
        __nv_bfloat16* tb = Xb; Xb = Xbn; Xbn = tb;
    }

    // 4b. residual-form polish, 2 iters: R = I - M*X (split), X += Xb*R (bf16)
    for (int it = 0; it < 2; it++) {
        xsp_rows_kernel<<<(NELEM/4)/256, 256>>>(Xf);
        mma_gemm_kernel<1><<<g2k, 256>>>(nullptr, pTbf, pMsp, pXspR, nullptr, nullptr,
                                         NN, K3, -1.0f, 0.0f, 1);          // Rbf = I - M*X
        mma_gemm_kernel<1><<<g2k, 256>>>(Xfn, Xbn, Xb, pTbf, Xf, nullptr,
                                         NN, NN, 1.0f, 1.0f, 0);           // Xn = X + Xb*R
        float* tf = Xf; Xf = Xfn; Xfn = tf;
        __nv_bfloat16* tb = Xb; Xb = Xbn; Xbn = tb;
    }

    // 5. W = 2X - I, split [hi|hi|lo]
    conv_W_split_kernel<<<(NELEM/4)/256, 256>>>(Xf);

    // 6. out = x W^T + bias  (split-bf16, K'=6144, K-major B)
    conv_splitA_kernel<<<((size_t)MBIG*NN/4)/256, 256>>>(x, pxsp, MBIG, NN);
    mma_gemm_kernel<0><<<dim3(NN/128, MBIG/128), 256>>>(out, nullptr, pxsp, pWsp, nullptr, bias,
                                                        NN, K3, 1.0f, 0.0f, 0);
}

// round 5
// speedup vs baseline: 5.8497x; 1.1512x over previous
#include <cuda_runtime.h>
#include <cuda_bf16.h>
#include <cstdint>

#define NN 2048
#define NELEM (NN*NN)
#define K3 (3*NN)
#define MBIG 8192
#define NSCALED 5

// ---------------- device scratch ----------------
__device__ float g_X[NELEM];
__device__ float g_Y[NELEM];
__device__ float g_M[NELEM];
__device__ __nv_bfloat16 g_Mbf[NELEM];
__device__ __nv_bfloat16 g_Tbf[NELEM];
__device__ __nv_bfloat16 g_Xbf0[NELEM];
__device__ __nv_bfloat16 g_Xbf1[NELEM];
__device__ __nv_bfloat16 g_Msp[(size_t)NN*K3];    // M split [hi|lo|hi] along k (A-op)
__device__ __nv_bfloat16 g_XspR[(size_t)K3*NN];   // X split rows [hi;hi;lo] (B-op, trans)
__device__ __nv_bfloat16 g_xsp[(size_t)MBIG*K3];  // x split [hi|lo|hi]
__device__ __nv_bfloat16 g_Wsp[(size_t)NN*K3];    // W split [hi|hi|lo]
__device__ float g_v[NN];
__device__ float g_u[NN];
__device__ float g_s[4];
__device__ float g_coef[2*NSCALED];               // per-iter (alpha=-s^2, beta=2s)

__device__ __forceinline__ uint32_t smem_u32(const void* p) {
    uint32_t a;
    asm("{ .reg .u64 t; cvta.to.shared.u64 t, %1; cvt.u32.u64 %0, t; }" : "=r"(a) : "l"(p));
    return a;
}

// ---------------- small kernels ----------------
__global__ void build_M_kernel(const float* __restrict__ w) {
    int j = blockIdx.x * blockDim.x + threadIdx.x;
    int i = blockIdx.y;
    float a = w[(size_t)i * NN + j] - w[(size_t)j * NN + i];
    float m = (i == j ? 1.0f : 0.0f) - a;
    g_M[(size_t)i * NN + j] = m;
    g_Mbf[(size_t)i * NN + j] = __float2bfloat16(m);
}

__global__ void init_v_kernel() {
    int i = blockIdx.x * blockDim.x + threadIdx.x;
    unsigned h = (unsigned)i * 2654435761u;
    h ^= h >> 16; h *= 2246822519u; h ^= h >> 13;
    g_v[i] = ((h & 0xFFFFFF) / 16777216.0f) - 0.5f;
}

// out = scale * (in - M@in) = scale * A@in
__global__ void matvec_A_kernel(int dst_is_u, float scale) {
    __shared__ float red[256];
    const float* in  = dst_is_u ? g_v : g_u;
    float*       out = dst_is_u ? g_u : g_v;
    int row = blockIdx.x;
    const __nv_bfloat162* Mrow = (const __nv_bfloat162*)(g_Mbf + (size_t)row * NN);
    float s = 0.f;
    #pragma unroll 4
    for (int j = threadIdx.x; j < NN/2; j += 256) {
        __nv_bfloat162 m2 = Mrow[j];
        s += __bfloat162float(m2.x) * in[2*j] + __bfloat162float(m2.y) * in[2*j+1];
    }
    red[threadIdx.x] = s;
    __syncthreads();
    for (int off = 128; off > 0; off >>= 1) {
        if (threadIdx.x < off) red[threadIdx.x] += red[threadIdx.x + off];
        __syncthreads();
    }
    if (threadIdx.x == 0) out[row] = scale * (in[row] - red[0]);
}

// sigma^2 -> c, plus the scaled-Newton coefficient schedule
__global__ void dots_and_c_kernel() {
    __shared__ float r0[1024], r1[1024];
    int t = threadIdx.x;
    float a = 0.f, b = 0.f;
    for (int i = t; i < NN; i += 1024) { float vv = g_v[i], uu = g_u[i]; a += vv*vv; b += uu*uu; }
    r0[t] = a; r1[t] = b;
    __syncthreads();
    for (int off = 512; off > 0; off >>= 1) {
        if (t < off) { r0[t] += r0[t+off]; r1[t] += r1[t+off]; }
        __syncthreads();
    }
    if (t == 0) {
        float sigma2 = r1[0] / (r0[0] + 1e-30f);
        float u = 1.5f * sigma2;                    // safety-inflated upper bound
        float c = 2.0f / (2.0f + u);
        g_s[2] = c;
        float lo = c, hi = c * (1.0f + u);          // spectrum interval of M*X0
        #pragma unroll
        for (int k = 0; k < NSCALED; k++) {
            float s = 2.0f / (lo + hi);
            g_coef[2*k]   = -s * s;                 // alpha
            g_coef[2*k+1] = 2.0f * s;               // beta
            float sl = s * lo;
            lo = sl * (2.0f - sl);
            hi = 1.0f;
        }
    }
}

__global__ void init_X0_kernel() {   // X0 = c * M^T  (fp32 + bf16)
    __shared__ float tile[32][33];
    int bx = blockIdx.x * 32, by = blockIdx.y * 32;
    #pragma unroll
    for (int dy = 0; dy < 32; dy += 8)
        tile[threadIdx.y + dy][threadIdx.x] = g_M[(size_t)(by + threadIdx.y + dy) * NN + bx + threadIdx.x];
    __syncthreads();
    float c = g_s[2];
    #pragma unroll
    for (int dy = 0; dy < 32; dy += 8) {
        float v = c * tile[threadIdx.x][threadIdx.y + dy];
        size_t off = (size_t)(bx + threadIdx.y + dy) * NN + by + threadIdx.x;
        g_X[off] = v;
        g_Xbf0[off] = __float2bfloat16(v);
    }
}

// split: src PxQ fp32 -> dst Px(3Q). [hi|lo|hi] along columns (A-op convention)
__global__ void conv_splitA_kernel(const float* __restrict__ src, __nv_bfloat16* __restrict__ dst,
                                   int P, int Q) {
    int t = blockIdx.x * blockDim.x + threadIdx.x;
    int nq = Q >> 2;
    if (t >= P * nq) return;
    int p = t / nq, q = (t % nq) * 4;
    float4 v = *(const float4*)(src + (size_t)p * Q + q);
    __nv_bfloat162 hi0, hi1, lo0, lo1;
    hi0.x = __float2bfloat16(v.x); lo0.x = __float2bfloat16(v.x - __bfloat162float(hi0.x));
    hi0.y = __float2bfloat16(v.y); lo0.y = __float2bfloat16(v.y - __bfloat162float(hi0.y));
    hi1.x = __float2bfloat16(v.z); lo1.x = __float2bfloat16(v.z - __bfloat162float(hi1.x));
    hi1.y = __float2bfloat16(v.w); lo1.y = __float2bfloat16(v.w - __bfloat162float(hi1.y));
    size_t ro = (size_t)p * 3 * Q + q;
    *(__nv_bfloat162*)(dst + ro)         = hi0;
    *(__nv_bfloat162*)(dst + ro + 2)     = hi1;
    *(__nv_bfloat162*)(dst + ro + Q)     = lo0;
    *(__nv_bfloat162*)(dst + ro + Q + 2) = lo1;
    *(__nv_bfloat162*)(dst + ro + 2*Q)     = hi0;
    *(__nv_bfloat162*)(dst + ro + 2*Q + 2) = hi1;
}

// X fp32 (NNxNN) -> XspR rows [hi; hi; lo]  (B-op for trans path)
__global__ void xsp_rows_kernel(const float* __restrict__ X) {
    int t = blockIdx.x * blockDim.x + threadIdx.x;
    int row = t >> 9, q = (t & 511) * 4;
    float4 v = *(const float4*)(X + (size_t)row * NN + q);
    __nv_bfloat162 hi0, hi1, lo0, lo1;
    hi0.x = __float2bfloat16(v.x); lo0.x = __float2bfloat16(v.x - __bfloat162float(hi0.x));
    hi0.y = __float2bfloat16(v.y); lo0.y = __float2bfloat16(v.y - __bfloat162float(hi0.y));
    hi1.x = __float2bfloat16(v.z); lo1.x = __float2bfloat16(v.z - __bfloat162float(hi1.x));
    hi1.y = __float2bfloat16(v.w); lo1.y = __float2bfloat16(v.w - __bfloat162float(hi1.y));
    size_t r0 = (size_t)row * NN + q;
    size_t r1 = (size_t)(NN + row) * NN + q;
    size_t r2 = (size_t)(2*NN + row) * NN + q;
    *(__nv_bfloat162*)(g_XspR + r0) = hi0; *(__nv_bfloat162*)(g_XspR + r0 + 2) = hi1;
    *(__nv_bfloat162*)(g_XspR + r1) = hi0; *(__nv_bfloat162*)(g_XspR + r1 + 2) = hi1;
    *(__nv_bfloat162*)(g_XspR + r2) = lo0; *(__nv_bfloat162*)(g_XspR + r2 + 2) = lo1;
}

// W = 2X - I, split [hi|hi|lo] along columns into g_Wsp
__global__ void conv_W_split_kernel(const float* __restrict__ X) {
    int t = blockIdx.x * blockDim.x + threadIdx.x;
    int o = t >> 9, i = (t & 511) * 4;
    float4 v = *(const float4*)(X + (size_t)o * NN + i);
    float w0 = 2.f*v.x - (o == i+0 ? 1.f : 0.f);
    float w1 = 2.f*v.y - (o == i+1 ? 1.f : 0.f);
    float w2 = 2.f*v.z - (o == i+2 ? 1.f : 0.f);
    float w3 = 2.f*v.w - (o == i+3 ? 1.f : 0.f);
    __nv_bfloat162 hi0, hi1, lo0, lo1;
    hi0.x = __float2bfloat16(w0); lo0.x = __float2bfloat16(w0 - __bfloat162float(hi0.x));
    hi0.y = __float2bfloat16(w1); lo0.y = __float2bfloat16(w1 - __bfloat162float(hi0.y));
    hi1.x = __float2bfloat16(w2); lo1.x = __float2bfloat16(w2 - __bfloat162float(hi1.x));
    hi1.y = __float2bfloat16(w3); lo1.y = __float2bfloat16(w3 - __bfloat162float(hi1.y));
    size_t ro = (size_t)o * K3 + i;
    *(__nv_bfloat162*)(g_Wsp + ro)          = hi0;
    *(__nv_bfloat162*)(g_Wsp + ro + 2)      = hi1;
    *(__nv_bfloat162*)(g_Wsp + ro + NN)     = hi0;
    *(__nv_bfloat162*)(g_Wsp + ro + NN + 2) = hi1;
    *(__nv_bfloat162*)(g_Wsp + ro + 2*NN)     = lo0;
    *(__nv_bfloat162*)(g_Wsp + ro + 2*NN + 2) = lo1;
}

// ---------------- mma.sync bf16 GEMM ----------------
// acc[m][n] = sum_k A[m][k]*B'[k][n]
//   BMODE 0: B K-major (non-trans ldmatrix); BMODE 1: B row-major (trans ldmatrix)
// (alpha,beta) from coefp if non-null (device-computed schedule), else host args.
#define SK 40
#define ASZ (128*SK*2)
#define BSZ 10240
#define BT_STRIDE 272
#define NSTAGE 3

template<int BMODE>
__global__ void __launch_bounds__(256, 2) mma_gemm_kernel(
    float* outF, __nv_bfloat16* outB,
    const __nv_bfloat16* __restrict__ A, const __nv_bfloat16* __restrict__ B,
    const float* __restrict__ Dext, const float* __restrict__ bias,
    const float* __restrict__ coefp,
    int Ndim, int Kdim, float alpha, float beta, int addI)
{
    __shared__ __align__(16) char smem[NSTAGE * (ASZ + BSZ)];
    uint32_t sbase = smem_u32(smem);
    int tid = threadIdx.x;
    int wid = tid >> 5, lid = tid & 31;
    int warp_m = wid >> 2, warp_n = wid & 3;
    int bm = blockIdx.y * 128, bn = blockIdx.x * 128;

    float acc[4][4][4];
    #pragma unroll
    for (int i = 0; i < 4; i++)
        #pragma unroll
        for (int j = 0; j < 4; j++)
            #pragma unroll
            for (int r = 0; r < 4; r++) acc[i][j][r] = 0.f;

    auto load_stage = [&](int stage, int kt) {
        uint32_t sA = sbase + stage * (ASZ + BSZ);
        uint32_t sB = sA + ASZ;
        #pragma unroll
        for (int s = 0; s < 2; s++) {
            int c = tid + s * 256;
            int row = c >> 2, kc = c & 3;
            const char* gA = (const char*)(A + (size_t)(bm + row) * Kdim + kt + kc * 8);
            uint32_t dA = sA + row * (SK*2) + kc * 16;
            asm volatile("cp.async.cg.shared.global [%0], [%1], 16;" :: "r"(dA), "l"(gA));
            if (BMODE == 0) {
                const char* gB = (const char*)(B + (size_t)(bn + row) * Kdim + kt + kc * 8);
                uint32_t dB = sB + row * (SK*2) + kc * 16;
                asm volatile("cp.async.cg.shared.global [%0], [%1], 16;" :: "r"(dB), "l"(gB));
            } else {
                int r = c >> 4, nch = c & 15;
                const char* gB = (const char*)(B + (size_t)(kt + r) * Ndim + bn + nch * 8);
                uint32_t dB = sB + r * BT_STRIDE + nch * 16;
                asm volatile("cp.async.cg.shared.global [%0], [%1], 16;" :: "r"(dB), "l"(gB));
            }
        }
        asm volatile("cp.async.commit_group;" ::: "memory");
    };

    const int NB = Kdim >> 5;
    load_stage(0, 0);
    load_stage(1, 32);

    uint32_t a_lane_off = (uint32_t)((lid & 15) * (SK*2) + ((lid >> 4) & 1) * 16);
    uint32_t b_lane_off0 = (uint32_t)((((lid & 7) + ((lid >> 4) & 1) * 8) * (SK*2)) + (((lid >> 3) & 1) * 16));
    int bg = lid >> 3, bw = lid & 7;
    uint32_t bt_krow = (uint32_t)((bg & 1) * 8 + bw);
    uint32_t bt_ncol = (uint32_t)((bg >> 1) * 8);

    for (int kb = 0; kb < NB; kb++) {
        if (kb >= NB - 2) asm volatile("cp.async.wait_group 0;" ::: "memory");
        else              asm volatile("cp.async.wait_group %0;" :: "n"(NSTAGE - 2) : "memory");
        __syncthreads();

        int stage = kb % NSTAGE;
        uint32_t sA = sbase + stage * (ASZ + BSZ) + warp_m * 64 * (SK*2);
        uint32_t sBb = sbase + stage * (ASZ + BSZ) + ASZ;

        #pragma unroll
        for (int kk = 0; kk < 2; kk++) {
            uint32_t af[4][4], bf[2][4];
            #pragma unroll
            for (int mi = 0; mi < 4; mi++) {
                uint32_t addr = sA + mi * 16 * (SK*2) + kk * 32 + a_lane_off;
                asm volatile("ldmatrix.sync.aligned.m8n8.x4.shared.b16 {%0,%1,%2,%3}, [%4];"
                    : "=r"(af[mi][0]), "=r"(af[mi][1]), "=r"(af[mi][2]), "=r"(af[mi][3]) : "r"(addr));
            }
            #pragma unroll
            for (int nj = 0; nj < 2; nj++) {
                if (BMODE == 0) {
                    uint32_t addr = sBb + (warp_n * 32 + nj * 16) * (SK*2) + kk * 32 + b_lane_off0;
                    asm volatile("ldmatrix.sync.aligned.m8n8.x4.shared.b16 {%0,%1,%2,%3}, [%4];"
                        : "=r"(bf[nj][0]), "=r"(bf[nj][1]), "=r"(bf[nj][2]), "=r"(bf[nj][3]) : "r"(addr));
                } else {
                    uint32_t addr = sBb + (kk * 16 + bt_krow) * BT_STRIDE
                                  + (warp_n * 32 + nj * 16 + bt_ncol) * 2;
                    asm volatile("ldmatrix.sync.aligned.m8n8.x4.trans.shared.b16 {%0,%1,%2,%3}, [%4];"
                        : "=r"(bf[nj][0]), "=r"(bf[nj][1]), "=r"(bf[nj][2]), "=r"(bf[nj][3]) : "r"(addr));
                }
            }
            #pragma unroll
            for (int mi = 0; mi < 4; mi++) {
                #pragma unroll
                for (int nj = 0; nj < 4; nj++) {
                    uint32_t b0 = bf[nj >> 1][(nj & 1) ? 2 : 0];
                    uint32_t b1 = bf[nj >> 1][(nj & 1) ? 3 : 1];
                    asm volatile(
                        "mma.sync.aligned.m16n8k16.row.col.f32.bf16.bf16.f32 "
                        "{%0,%1,%2,%3}, {%4,%5,%6,%7}, {%8,%9}, {%0,%1,%2,%3};"
                        : "+f"(acc[mi][nj][0]), "+f"(acc[mi][nj][1]),
                          "+f"(acc[mi][nj][2]), "+f"(acc[mi][nj][3])
                        : "r"(af[mi][0]), "r"(af[mi][1]), "r"(af[mi][2]), "r"(af[mi][3]),
                          "r"(b0), "r"(b1));
                }
            }
        }
        __syncthreads();
        if (kb + 2 < NB) load_stage((kb + 2) % NSTAGE, (kb + 2) * 32);
    }

    if (coefp) { alpha = coefp[0]; beta = coefp[1]; }

    int lrow = lid >> 2, lcol = (lid & 3) * 2;
    #pragma unroll
    for (int mi = 0; mi < 4; mi++) {
        #pragma unroll
        for (int half = 0; half < 2; half++) {
            int row = bm + warp_m * 64 + mi * 16 + lrow + half * 8;
            #pragma unroll
            for (int nj = 0; nj < 4; nj++) {
                int col = bn + warp_n * 32 + nj * 8 + lcol;
                size_t off = (size_t)row * Ndim + col;
                float2 o;
                o.x = alpha * acc[mi][nj][half * 2 + 0];
                o.y = alpha * acc[mi][nj][half * 2 + 1];
                if (Dext) {
                    float2 d2 = *(const float2*)(Dext + off);
                    o.x += beta * d2.x; o.y += beta * d2.y;
                }
                if (bias) {
                    float2 b2 = *(const float2*)(bias + col);
                    o.x += b2.x; o.y += b2.y;
                }
                if (addI) {
                    if (row == col)     o.x += 1.f;
                    if (row == col + 1) o.y += 1.f;
                }
                if (outF) *(float2*)(outF + off) = o;
                if (outB) {
                    __nv_bfloat162 h;
                    h.x = __float2bfloat16(o.x); h.y = __float2bfloat16(o.y);
                    *(__nv_bfloat162*)(outB + off) = h;
                }
            }
        }
    }
}

// ---------------- launch ----------------
extern "C" void kernel_launch(void* const* d_in, const int* in_sizes, int n_in,
                              void* d_out, int out_size) {
    const float* x      = (const float*)d_in[0];
    const float* weight = (const float*)d_in[1];
    const float* bias   = (const float*)d_in[2];
    float* out = (float*)d_out;

    float *pX, *pY, *pM, *pCoef;
    __nv_bfloat16 *pMbf, *pTbf, *pXbf0, *pXbf1, *pMsp, *pXspR, *pxsp, *pWsp;
    cudaGetSymbolAddress((void**)&pX, g_X);
    cudaGetSymbolAddress((void**)&pY, g_Y);
    cudaGetSymbolAddress((void**)&pM, g_M);
    cudaGetSymbolAddress((void**)&pCoef, g_coef);
    cudaGetSymbolAddress((void**)&pMbf, g_Mbf);
    cudaGetSymbolAddress((void**)&pTbf, g_Tbf);
    cudaGetSymbolAddress((void**)&pXbf0, g_Xbf0);
    cudaGetSymbolAddress((void**)&pXbf1, g_Xbf1);
    cudaGetSymbolAddress((void**)&pMsp, g_Msp);
    cudaGetSymbolAddress((void**)&pXspR, g_XspR);
    cudaGetSymbolAddress((void**)&pxsp, g_xsp);
    cudaGetSymbolAddress((void**)&pWsp, g_Wsp);

    // 1. M = I - (w - w^T)
    build_M_kernel<<<dim3(NN/256, NN), 256>>>(weight);

    // 2. power iteration (6 pairs) -> sigma^2, c, scaled-Newton schedule
    init_v_kernel<<<NN/256, 256>>>();
    for (int it = 0; it < 6; it++) {
        matvec_A_kernel<<<NN, 256>>>(1, 1.0f);
        matvec_A_kernel<<<NN, 256>>>(0, 1.0f / 64.0f);
    }
    matvec_A_kernel<<<NN, 256>>>(1, 1.0f);
    dots_and_c_kernel<<<1, 1024>>>();

    // 3. X0 = c * M^T (fp32 + bf16)
    init_X0_kernel<<<dim3(NN/32, NN/32), dim3(32, 8)>>>();

    // M split for polish
    conv_splitA_kernel<<<(NELEM/4)/256, 256>>>(pM, pMsp, NN, NN);

    dim3 g2k(NN/128, NN/128);
    float *Xf = pX, *Xfn = pY;
    __nv_bfloat16 *Xb = pXbf0, *Xbn = pXbf1;

    // 4a. scaled Newton bf16: 5 iters, coefficients from device schedule
    for (int it = 0; it < NSCALED; it++) {
        mma_gemm_kernel<1><<<g2k, 256>>>(nullptr, pTbf, pMbf, Xb, nullptr, nullptr, nullptr,
                                         NN, NN, 1.0f, 0.0f, 0);            // T = M*Xb
        mma_gemm_kernel<1><<<g2k, 256>>>(Xfn, Xbn, Xb, pTbf, Xf, nullptr, pCoef + 2*it,
                                         NN, NN, 0.f, 0.f, 0);              // Xn = 2s*X - s^2*Xb*T
        float* tf = Xf; Xf = Xfn; Xfn = tf;
        __nv_bfloat16* tb = Xb; Xb = Xbn; Xbn = tb;
    }

    // 4b. residual-form polish, 2 iters: R = I - M*X (split), X += Xb*R
    for (int it = 0; it < 2; it++) {
        xsp_rows_kernel<<<(NELEM/4)/256, 256>>>(Xf);
        mma_gemm_kernel<1><<<g2k, 256>>>(nullptr, pTbf, pMsp, pXspR, nullptr, nullptr, nullptr,
                                         NN, K3, -1.0f, 0.0f, 1);           // Rbf = I - M*X
        mma_gemm_kernel<1><<<g2k, 256>>>(Xfn, Xbn, Xb, pTbf, Xf, nullptr, nullptr,
                                         NN, NN, 1.0f, 1.0f, 0);            // Xn = X + Xb*R
        float* tf = Xf; Xf = Xfn; Xfn = tf;
        __nv_bfloat16* tb = Xb; Xb = Xbn; Xbn = tb;
    }

    // 5. W = 2X - I, split [hi|hi|lo]
    conv_W_split_kernel<<<(NELEM/4)/256, 256>>>(Xf);

    // 6. out = x W^T + bias  (split-bf16, K'=6144)
    conv_splitA_kernel<<<((size_t)MBIG*NN/4)/256, 256>>>(x, pxsp, MBIG, NN);
    mma_gemm_kernel<0><<<dim3(NN/128, MBIG/128), 256>>>(out, nullptr, pxsp, pWsp, nullptr, bias, nullptr,
                                                        NN, K3, 1.0f, 0.0f, 0);
}

// round 6
// speedup vs baseline: 6.5684x; 1.1229x over previous
#include <cuda_runtime.h>
#include <cuda_bf16.h>
#include <cstdint>

#define NN 2048
#define NELEM (NN*NN)
#define MBIG 8192
#define NSCALED 5

// ---------------- device scratch ----------------
__device__ float g_X[NELEM];
__device__ float g_Y[NELEM];
__device__ float g_M[NELEM];
__device__ __nv_bfloat16 g_Mbf[NELEM];    // M hi
__device__ __nv_bfloat16 g_Mlo[NELEM];    // M lo
__device__ __nv_bfloat16 g_Tbf[NELEM];
__device__ __nv_bfloat16 g_Xbf0[NELEM];   // X hi ping
__device__ __nv_bfloat16 g_Xbf1[NELEM];   // X hi pong
__device__ __nv_bfloat16 g_Xlo0[NELEM];   // X lo ping
__device__ __nv_bfloat16 g_Xlo1[NELEM];   // X lo pong
__device__ __nv_bfloat16 g_xhi[(size_t)MBIG*NN];
__device__ __nv_bfloat16 g_xlo[(size_t)MBIG*NN];
__device__ __nv_bfloat16 g_Whi[NELEM];
__device__ __nv_bfloat16 g_Wlo[NELEM];
__device__ float g_v[NN];
__device__ float g_u[NN];
__device__ float g_s[4];
__device__ float g_coef[2*NSCALED];

__device__ __forceinline__ uint32_t smem_u32(const void* p) {
    uint32_t a;
    asm("{ .reg .u64 t; cvta.to.shared.u64 t, %1; cvt.u32.u64 %0, t; }" : "=r"(a) : "l"(p));
    return a;
}

// ---------------- small kernels ----------------
__global__ void build_M_kernel(const float* __restrict__ w) {
    int j = blockIdx.x * blockDim.x + threadIdx.x;
    int i = blockIdx.y;
    float a = w[(size_t)i * NN + j] - w[(size_t)j * NN + i];
    float m = (i == j ? 1.0f : 0.0f) - a;
    size_t off = (size_t)i * NN + j;
    g_M[off] = m;
    __nv_bfloat16 hi = __float2bfloat16(m);
    g_Mbf[off] = hi;
    g_Mlo[off] = __float2bfloat16(m - __bfloat162float(hi));
}

__global__ void init_v_kernel() {
    int i = blockIdx.x * blockDim.x + threadIdx.x;
    unsigned h = (unsigned)i * 2654435761u;
    h ^= h >> 16; h *= 2246822519u; h ^= h >> 13;
    g_v[i] = ((h & 0xFFFFFF) / 16777216.0f) - 0.5f;
}

// out = scale * (in - M@in) = scale * A@in
__global__ void matvec_A_kernel(int dst_is_u, float scale) {
    __shared__ float red[256];
    const float* in  = dst_is_u ? g_v : g_u;
    float*       out = dst_is_u ? g_u : g_v;
    int row = blockIdx.x;
    const __nv_bfloat162* Mrow = (const __nv_bfloat162*)(g_Mbf + (size_t)row * NN);
    float s = 0.f;
    #pragma unroll 4
    for (int j = threadIdx.x; j < NN/2; j += 256) {
        __nv_bfloat162 m2 = Mrow[j];
        s += __bfloat162float(m2.x) * in[2*j] + __bfloat162float(m2.y) * in[2*j+1];
    }
    red[threadIdx.x] = s;
    __syncthreads();
    for (int off = 128; off > 0; off >>= 1) {
        if (threadIdx.x < off) red[threadIdx.x] += red[threadIdx.x + off];
        __syncthreads();
    }
    if (threadIdx.x == 0) out[row] = scale * (in[row] - red[0]);
}

// sigma^2 -> c + scaled-Newton coefficient schedule
__global__ void dots_and_c_kernel() {
    __shared__ float r0[1024], r1[1024];
    int t = threadIdx.x;
    float a = 0.f, b = 0.f;
    for (int i = t; i < NN; i += 1024) { float vv = g_v[i], uu = g_u[i]; a += vv*vv; b += uu*uu; }
    r0[t] = a; r1[t] = b;
    __syncthreads();
    for (int off = 512; off > 0; off >>= 1) {
        if (t < off) { r0[t] += r0[t+off]; r1[t] += r1[t+off]; }
        __syncthreads();
    }
    if (t == 0) {
        float sigma2 = r1[0] / (r0[0] + 1e-30f);
        float u = 1.6f * sigma2;                    // safety-inflated upper bound
        float c = 2.0f / (2.0f + u);
        g_s[2] = c;
        float lo = c, hi = c * (1.0f + u);
        #pragma unroll
        for (int k = 0; k < NSCALED; k++) {
            float s = 2.0f / (lo + hi);
            g_coef[2*k]   = -s * s;
            g_coef[2*k+1] = 2.0f * s;
            float sl = s * lo;
            lo = sl * (2.0f - sl);
            hi = 1.0f;
        }
    }
}

__global__ void init_X0_kernel() {   // X0 = c * M^T  (fp32 + bf16 hi/lo)
    __shared__ float tile[32][33];
    int bx = blockIdx.x * 32, by = blockIdx.y * 32;
    #pragma unroll
    for (int dy = 0; dy < 32; dy += 8)
        tile[threadIdx.y + dy][threadIdx.x] = g_M[(size_t)(by + threadIdx.y + dy) * NN + bx + threadIdx.x];
    __syncthreads();
    float c = g_s[2];
    #pragma unroll
    for (int dy = 0; dy < 32; dy += 8) {
        float v = c * tile[threadIdx.x][threadIdx.y + dy];
        size_t off = (size_t)(bx + threadIdx.y + dy) * NN + by + threadIdx.x;
        g_X[off] = v;
        __nv_bfloat16 hi = __float2bfloat16(v);
        g_Xbf0[off] = hi;
        g_Xlo0[off] = __float2bfloat16(v - __bfloat162float(hi));
    }
}

// x fp32 -> xhi, xlo arrays
__global__ void conv_xsplit_kernel(const float* __restrict__ x) {
    size_t i = ((size_t)blockIdx.x * blockDim.x + threadIdx.x) * 4;
    float4 v = *(const float4*)(x + i);
    __nv_bfloat162 hi0, hi1, lo0, lo1;
    hi0.x = __float2bfloat16(v.x); lo0.x = __float2bfloat16(v.x - __bfloat162float(hi0.x));
    hi0.y = __float2bfloat16(v.y); lo0.y = __float2bfloat16(v.y - __bfloat162float(hi0.y));
    hi1.x = __float2bfloat16(v.z); lo1.x = __float2bfloat16(v.z - __bfloat162float(hi1.x));
    hi1.y = __float2bfloat16(v.w); lo1.y = __float2bfloat16(v.w - __bfloat162float(hi1.y));
    *(__nv_bfloat162*)(g_xhi + i)     = hi0;
    *(__nv_bfloat162*)(g_xhi + i + 2) = hi1;
    *(__nv_bfloat162*)(g_xlo + i)     = lo0;
    *(__nv_bfloat162*)(g_xlo + i + 2) = lo1;
}

// W = 2X - I -> Whi, Wlo arrays
__global__ void conv_W_kernel(const float* __restrict__ X) {
    int t = blockIdx.x * blockDim.x + threadIdx.x;
    int o = t >> 9, i = (t & 511) * 4;
    float4 v = *(const float4*)(X + (size_t)o * NN + i);
    float w0 = 2.f*v.x - (o == i+0 ? 1.f : 0.f);
    float w1 = 2.f*v.y - (o == i+1 ? 1.f : 0.f);
    float w2 = 2.f*v.z - (o == i+2 ? 1.f : 0.f);
    float w3 = 2.f*v.w - (o == i+3 ? 1.f : 0.f);
    __nv_bfloat162 hi0, hi1, lo0, lo1;
    hi0.x = __float2bfloat16(w0); lo0.x = __float2bfloat16(w0 - __bfloat162float(hi0.x));
    hi0.y = __float2bfloat16(w1); lo0.y = __float2bfloat16(w1 - __bfloat162float(hi0.y));
    hi1.x = __float2bfloat16(w2); lo1.x = __float2bfloat16(w2 - __bfloat162float(hi1.x));
    hi1.y = __float2bfloat16(w3); lo1.y = __float2bfloat16(w3 - __bfloat162float(hi1.y));
    size_t ro = (size_t)o * NN + i;
    *(__nv_bfloat162*)(g_Whi + ro)     = hi0;
    *(__nv_bfloat162*)(g_Whi + ro + 2) = hi1;
    *(__nv_bfloat162*)(g_Wlo + ro)     = lo0;
    *(__nv_bfloat162*)(g_Wlo + ro + 2) = lo1;
}

// ---------------- mma.sync bf16 GEMM with segmented operands ----------------
// acc[m][n] = sum_k Aseg(kt>>11)[m][kt&2047] * Bseg(kt>>11)'[kt&2047][n]
//   BMODE 0: B K-major (row stride NN); BMODE 1: B row-major (row stride Ndim), trans ldmatrix
// A row stride always NN. (alpha,beta) from coefp if non-null.
#define SK 40
#define ASZ (128*SK*2)
#define BSZ 10240
#define BT_STRIDE 272
#define NSTAGE 3

template<int BMODE>
__global__ void __launch_bounds__(256, 2) mma_gemm_kernel(
    float* outF, __nv_bfloat16* outB, __nv_bfloat16* outBlo,
    const __nv_bfloat16* __restrict__ A0, const __nv_bfloat16* __restrict__ A1,
    const __nv_bfloat16* __restrict__ A2,
    const __nv_bfloat16* __restrict__ B0, const __nv_bfloat16* __restrict__ B1,
    const __nv_bfloat16* __restrict__ B2,
    const float* __restrict__ Dext, const float* __restrict__ bias,
    const float* __restrict__ coefp,
    int Ndim, int Kdim, float alpha, float beta, int addI)
{
    __shared__ __align__(16) char smem[NSTAGE * (ASZ + BSZ)];
    uint32_t sbase = smem_u32(smem);
    int tid = threadIdx.x;
    int wid = tid >> 5, lid = tid & 31;
    int warp_m = wid >> 2, warp_n = wid & 3;
    int bm = blockIdx.y * 128, bn = blockIdx.x * 128;

    float acc[4][4][4];
    #pragma unroll
    for (int i = 0; i < 4; i++)
        #pragma unroll
        for (int j = 0; j < 4; j++)
            #pragma unroll
            for (int r = 0; r < 4; r++) acc[i][j][r] = 0.f;

    auto load_stage = [&](int stage, int kt) {
        int seg = kt >> 11;
        int kc0 = kt & (NN - 1);
        const __nv_bfloat16* As = (seg == 0) ? A0 : ((seg == 1) ? A1 : A2);
        const __nv_bfloat16* Bs = (seg == 0) ? B0 : ((seg == 1) ? B1 : B2);
        uint32_t sA = sbase + stage * (ASZ + BSZ);
        uint32_t sB = sA + ASZ;
        #pragma unroll
        for (int s = 0; s < 2; s++) {
            int c = tid + s * 256;
            int row = c >> 2, kc = c & 3;
            const char* gA = (const char*)(As + (size_t)(bm + row) * NN + kc0 + kc * 8);
            uint32_t dA = sA + row * (SK*2) + kc * 16;
            asm volatile("cp.async.cg.shared.global [%0], [%1], 16;" :: "r"(dA), "l"(gA));
            if (BMODE == 0) {
                const char* gB = (const char*)(Bs + (size_t)(bn + row) * NN + kc0 + kc * 8);
                uint32_t dB = sB + row * (SK*2) + kc * 16;
                asm volatile("cp.async.cg.shared.global [%0], [%1], 16;" :: "r"(dB), "l"(gB));
            } else {
                int r = c >> 4, nch = c & 15;
                const char* gB = (const char*)(Bs + (size_t)(kc0 + r) * Ndim + bn + nch * 8);
                uint32_t dB = sB + r * BT_STRIDE + nch * 16;
                asm volatile("cp.async.cg.shared.global [%0], [%1], 16;" :: "r"(dB), "l"(gB));
            }
        }
        asm volatile("cp.async.commit_group;" ::: "memory");
    };

    const int NB = Kdim >> 5;
    load_stage(0, 0);
    load_stage(1, 32);

    uint32_t a_lane_off = (uint32_t)((lid & 15) * (SK*2) + ((lid >> 4) & 1) * 16);
    uint32_t b_lane_off0 = (uint32_t)((((lid & 7) + ((lid >> 4) & 1) * 8) * (SK*2)) + (((lid >> 3) & 1) * 16));
    int bg = lid >> 3, bw = lid & 7;
    uint32_t bt_krow = (uint32_t)((bg & 1) * 8 + bw);
    uint32_t bt_ncol = (uint32_t)((bg >> 1) * 8);

    for (int kb = 0; kb < NB; kb++) {
        if (kb >= NB - 2) asm volatile("cp.async.wait_group 0;" ::: "memory");
        else              asm volatile("cp.async.wait_group %0;" :: "n"(NSTAGE - 2) : "memory");
        __syncthreads();

        int stage = kb % NSTAGE;
        uint32_t sA = sbase + stage * (ASZ + BSZ) + warp_m * 64 * (SK*2);
        uint32_t sBb = sbase + stage * (ASZ + BSZ) + ASZ;

        #pragma unroll
        for (int kk = 0; kk < 2; kk++) {
            uint32_t af[4][4], bf[2][4];
            #pragma unroll
            for (int mi = 0; mi < 4; mi++) {
                uint32_t addr = sA + mi * 16 * (SK*2) + kk * 32 + a_lane_off;
                asm volatile("ldmatrix.sync.aligned.m8n8.x4.shared.b16 {%0,%1,%2,%3}, [%4];"
                    : "=r"(af[mi][0]), "=r"(af[mi][1]), "=r"(af[mi][2]), "=r"(af[mi][3]) : "r"(addr));
            }
            #pragma unroll
            for (int nj = 0; nj < 2; nj++) {
                if (BMODE == 0) {
                    uint32_t addr = sBb + (warp_n * 32 + nj * 16) * (SK*2) + kk * 32 + b_lane_off0;
                    asm volatile("ldmatrix.sync.aligned.m8n8.x4.shared.b16 {%0,%1,%2,%3}, [%4];"
                        : "=r"(bf[nj][0]), "=r"(bf[nj][1]), "=r"(bf[nj][2]), "=r"(bf[nj][3]) : "r"(addr));
                } else {
                    uint32_t addr = sBb + (kk * 16 + bt_krow) * BT_STRIDE
                                  + (warp_n * 32 + nj * 16 + bt_ncol) * 2;
                    asm volatile("ldmatrix.sync.aligned.m8n8.x4.trans.shared.b16 {%0,%1,%2,%3}, [%4];"
                        : "=r"(bf[nj][0]), "=r"(bf[nj][1]), "=r"(bf[nj][2]), "=r"(bf[nj][3]) : "r"(addr));
                }
            }
            #pragma unroll
            for (int mi = 0; mi < 4; mi++) {
                #pragma unroll
                for (int nj = 0; nj < 4; nj++) {
                    uint32_t b0 = bf[nj >> 1][(nj & 1) ? 2 : 0];
                    uint32_t b1 = bf[nj >> 1][(nj & 1) ? 3 : 1];
                    asm volatile(
                        "mma.sync.aligned.m16n8k16.row.col.f32.bf16.bf16.f32 "
                        "{%0,%1,%2,%3}, {%4,%5,%6,%7}, {%8,%9}, {%0,%1,%2,%3};"
                        : "+f"(acc[mi][nj][0]), "+f"(acc[mi][nj][1]),
                          "+f"(acc[mi][nj][2]), "+f"(acc[mi][nj][3])
                        : "r"(af[mi][0]), "r"(af[mi][1]), "r"(af[mi][2]), "r"(af[mi][3]),
                          "r"(b0), "r"(b1));
                }
            }
        }
        __syncthreads();
        if (kb + 2 < NB) load_stage((kb + 2) % NSTAGE, (kb + 2) * 32);
    }

    if (coefp) { alpha = coefp[0]; beta = coefp[1]; }

    int lrow = lid >> 2, lcol = (lid & 3) * 2;
    #pragma unroll
    for (int mi = 0; mi < 4; mi++) {
        #pragma unroll
        for (int half = 0; half < 2; half++) {
            int row = bm + warp_m * 64 + mi * 16 + lrow + half * 8;
            #pragma unroll
            for (int nj = 0; nj < 4; nj++) {
                int col = bn + warp_n * 32 + nj * 8 + lcol;
                size_t off = (size_t)row * Ndim + col;
                float2 o;
                o.x = alpha * acc[mi][nj][half * 2 + 0];
                o.y = alpha * acc[mi][nj][half * 2 + 1];
                if (Dext) {
                    float2 d2 = *(const float2*)(Dext + off);
                    o.x += beta * d2.x; o.y += beta * d2.y;
                }
                if (bias) {
                    float2 b2 = *(const float2*)(bias + col);
                    o.x += b2.x; o.y += b2.y;
                }
                if (addI) {
                    if (row == col)     o.x += 1.f;
                    if (row == col + 1) o.y += 1.f;
                }
                if (outF) *(float2*)(outF + off) = o;
                if (outB || outBlo) {
                    __nv_bfloat162 h;
                    h.x = __float2bfloat16(o.x); h.y = __float2bfloat16(o.y);
                    if (outB) *(__nv_bfloat162*)(outB + off) = h;
                    if (outBlo) {
                        __nv_bfloat162 l;
                        l.x = __float2bfloat16(o.x - __bfloat162float(h.x));
                        l.y = __float2bfloat16(o.y - __bfloat162float(h.y));
                        *(__nv_bfloat162*)(outBlo + off) = l;
                    }
                }
            }
        }
    }
}

// ---------------- launch ----------------
extern "C" void kernel_launch(void* const* d_in, const int* in_sizes, int n_in,
                              void* d_out, int out_size) {
    const float* x      = (const float*)d_in[0];
    const float* weight = (const float*)d_in[1];
    const float* bias   = (const float*)d_in[2];
    float* out = (float*)d_out;

    float *pX, *pY, *pCoef;
    __nv_bfloat16 *pMbf, *pMlo, *pTbf, *pXb0, *pXb1, *pXl0, *pXl1, *pxhi, *pxlo, *pWhi, *pWlo;
    cudaGetSymbolAddress((void**)&pX, g_X);
    cudaGetSymbolAddress((void**)&pY, g_Y);
    cudaGetSymbolAddress((void**)&pCoef, g_coef);
    cudaGetSymbolAddress((void**)&pMbf, g_Mbf);
    cudaGetSymbolAddress((void**)&pMlo, g_Mlo);
    cudaGetSymbolAddress((void**)&pTbf, g_Tbf);
    cudaGetSymbolAddress((void**)&pXb0, g_Xbf0);
    cudaGetSymbolAddress((void**)&pXb1, g_Xbf1);
    cudaGetSymbolAddress((void**)&pXl0, g_Xlo0);
    cudaGetSymbolAddress((void**)&pXl1, g_Xlo1);
    cudaGetSymbolAddress((void**)&pxhi, g_xhi);
    cudaGetSymbolAddress((void**)&pxlo, g_xlo);
    cudaGetSymbolAddress((void**)&pWhi, g_Whi);
    cudaGetSymbolAddress((void**)&pWlo, g_Wlo);

    // 1. M = I - (w - w^T)  (fp32 + bf16 hi/lo)
    build_M_kernel<<<dim3(NN/256, NN), 256>>>(weight);

    // 2. power iteration (4 pairs) -> sigma^2, c, schedule
    init_v_kernel<<<NN/256, 256>>>();
    for (int it = 0; it < 4; it++) {
        matvec_A_kernel<<<NN, 256>>>(1, 1.0f);
        matvec_A_kernel<<<NN, 256>>>(0, 1.0f / 64.0f);
    }
    matvec_A_kernel<<<NN, 256>>>(1, 1.0f);
    dots_and_c_kernel<<<1, 1024>>>();

    // 3. X0 = c * M^T (fp32 + bf16 hi/lo)
    init_X0_kernel<<<dim3(NN/32, NN/32), dim3(32, 8)>>>();

    dim3 g2k(NN/128, NN/128);
    float *Xf = pX, *Xfn = pY;
    __nv_bfloat16 *Xb = pXb0, *Xbn = pXb1;
    __nv_bfloat16 *Xl = pXl0, *Xln = pXl1;

    // 4a. scaled Newton bf16, 5 iters (epilogue maintains hi+lo split of X)
    for (int it = 0; it < NSCALED; it++) {
        mma_gemm_kernel<1><<<g2k, 256>>>(nullptr, pTbf, nullptr,
                                         pMbf, pMbf, pMbf, Xb, Xb, Xb,
                                         nullptr, nullptr, nullptr,
                                         NN, NN, 1.0f, 0.0f, 0);            // T = M*Xb
        mma_gemm_kernel<1><<<g2k, 256>>>(Xfn, Xbn, Xln,
                                         Xb, Xb, Xb, pTbf, pTbf, pTbf,
                                         Xf, nullptr, pCoef + 2*it,
                                         NN, NN, 0.f, 0.f, 0);              // Xn = 2s*X - s^2*Xb*T
        float* tf = Xf; Xf = Xfn; Xfn = tf;
        __nv_bfloat16* tb = Xb; Xb = Xbn; Xbn = tb;
        __nv_bfloat16* tl = Xl; Xl = Xln; Xln = tl;
    }

    // 4b. single strengthened polish:
    //   R = I - M*X   (segments: Mhi*Xhi + Mlo*Xhi + Mhi*Xlo, K=6144)
    mma_gemm_kernel<1><<<g2k, 256>>>(nullptr, pTbf, nullptr,
                                     pMbf, pMlo, pMbf, Xb, Xb, Xl,
                                     nullptr, nullptr, nullptr,
                                     NN, 3*NN, -1.0f, 0.0f, 1);
    //   Xn = Xf + [Xhi|Xlo]*[R;R]   (K=4096, split X removes bf16 update noise)
    mma_gemm_kernel<1><<<g2k, 256>>>(Xfn, nullptr, nullptr,
                                     Xb, Xl, Xl, pTbf, pTbf, pTbf,
                                     Xf, nullptr, nullptr,
                                     NN, 2*NN, 1.0f, 1.0f, 0);
    { float* tf = Xf; Xf = Xfn; Xfn = tf; }

    // 5. W = 2X - I -> Whi, Wlo
    conv_W_kernel<<<NELEM/4/256, 256>>>(Xf);

    // 6. out = x W^T + bias  (segments: xhi*Whi + xlo*Whi + xhi*Wlo, K=6144)
    conv_xsplit_kernel<<<((size_t)MBIG*NN/4)/256, 256>>>(x);
    mma_gemm_kernel<0><<<dim3(NN/128, MBIG/128), 256>>>(out, nullptr, nullptr,
                                                        pxhi, pxlo, pxhi, pWhi, pWhi, pWlo,
                                                        nullptr, bias, nullptr,
                                                        NN, 3*NN, 1.0f, 0.0f, 0);
}

// round 7
// speedup vs baseline: 6.6857x; 1.0179x over previous
#include <cuda_runtime.h>
#include <cuda_bf16.h>
#include <cstdint>

#define NN 2048
#define NELEM (NN*NN)
#define MBIG 8192
#define NSCALED 5

// ---------------- device scratch ----------------
__device__ float g_X[NELEM];
__device__ float g_Y[NELEM];
__device__ float g_M[NELEM];
__device__ __nv_bfloat16 g_Mbf[NELEM];    // M hi
__device__ __nv_bfloat16 g_Mlo[NELEM];    // M lo
__device__ __nv_bfloat16 g_Tbf[NELEM];
__device__ __nv_bfloat16 g_Xbf0[NELEM];   // X hi ping
__device__ __nv_bfloat16 g_Xbf1[NELEM];   // X hi pong
__device__ __nv_bfloat16 g_Xlo0[NELEM];   // X lo ping
__device__ __nv_bfloat16 g_Xlo1[NELEM];   // X lo pong
__device__ __nv_bfloat16 g_xhi[(size_t)MBIG*NN];
__device__ __nv_bfloat16 g_xlo[(size_t)MBIG*NN];
__device__ float g_v[NN];
__device__ float g_u[NN];
__device__ float g_s[4];
__device__ float g_coef[2*NSCALED];

__device__ __forceinline__ uint32_t smem_u32(const void* p) {
    uint32_t a;
    asm("{ .reg .u64 t; cvta.to.shared.u64 t, %1; cvt.u32.u64 %0, t; }" : "=r"(a) : "l"(p));
    return a;
}

// ---------------- small kernels ----------------
__global__ void build_M_kernel(const float* __restrict__ w) {
    int j = blockIdx.x * blockDim.x + threadIdx.x;
    int i = blockIdx.y;
    float a = w[(size_t)i * NN + j] - w[(size_t)j * NN + i];
    float m = (i == j ? 1.0f : 0.0f) - a;
    size_t off = (size_t)i * NN + j;
    g_M[off] = m;
    __nv_bfloat16 hi = __float2bfloat16(m);
    g_Mbf[off] = hi;
    g_Mlo[off] = __float2bfloat16(m - __bfloat162float(hi));
}

__global__ void init_v_kernel() {
    int i = blockIdx.x * blockDim.x + threadIdx.x;
    unsigned h = (unsigned)i * 2654435761u;
    h ^= h >> 16; h *= 2246822519u; h ^= h >> 13;
    g_v[i] = ((h & 0xFFFFFF) / 16777216.0f) - 0.5f;
}

// out = scale * (in - M@in) = scale * A@in   (one warp per row)
__global__ void matvec_A_kernel(int dst_is_u, float scale) {
    const float* in  = dst_is_u ? g_v : g_u;
    float*       out = dst_is_u ? g_u : g_v;
    int row = blockIdx.x * 8 + (threadIdx.x >> 5);
    int lid = threadIdx.x & 31;
    const __nv_bfloat162* Mrow = (const __nv_bfloat162*)(g_Mbf + (size_t)row * NN);
    float s = 0.f;
    #pragma unroll 8
    for (int j = lid; j < NN/2; j += 32) {
        __nv_bfloat162 m2 = Mrow[j];
        s += __bfloat162float(m2.x) * in[2*j] + __bfloat162float(m2.y) * in[2*j+1];
    }
    #pragma unroll
    for (int o = 16; o > 0; o >>= 1) s += __shfl_xor_sync(0xFFFFFFFFu, s, o);
    if (lid == 0) out[row] = scale * (in[row] - s);
}

// sigma^2 -> c + scaled-Newton coefficient schedule
__global__ void dots_and_c_kernel() {
    __shared__ float r0[1024], r1[1024];
    int t = threadIdx.x;
    float a = 0.f, b = 0.f;
    for (int i = t; i < NN; i += 1024) { float vv = g_v[i], uu = g_u[i]; a += vv*vv; b += uu*uu; }
    r0[t] = a; r1[t] = b;
    __syncthreads();
    for (int off = 512; off > 0; off >>= 1) {
        if (t < off) { r0[t] += r0[t+off]; r1[t] += r1[t+off]; }
        __syncthreads();
    }
    if (t == 0) {
        float sigma2 = r1[0] / (r0[0] + 1e-30f);
        float u = 1.6f * sigma2;
        float c = 2.0f / (2.0f + u);
        g_s[2] = c;
        float lo = c, hi = c * (1.0f + u);
        #pragma unroll
        for (int k = 0; k < NSCALED; k++) {
            float s = 2.0f / (lo + hi);
            g_coef[2*k]   = -s * s;
            g_coef[2*k+1] = 2.0f * s;
            float sl = s * lo;
            lo = sl * (2.0f - sl);
            hi = 1.0f;
        }
    }
}

__global__ void init_X0_kernel() {   // X0 = c * M^T  (fp32 + bf16 hi)
    __shared__ float tile[32][33];
    int bx = blockIdx.x * 32, by = blockIdx.y * 32;
    #pragma unroll
    for (int dy = 0; dy < 32; dy += 8)
        tile[threadIdx.y + dy][threadIdx.x] = g_M[(size_t)(by + threadIdx.y + dy) * NN + bx + threadIdx.x];
    __syncthreads();
    float c = g_s[2];
    #pragma unroll
    for (int dy = 0; dy < 32; dy += 8) {
        float v = c * tile[threadIdx.x][threadIdx.y + dy];
        size_t off = (size_t)(bx + threadIdx.y + dy) * NN + by + threadIdx.x;
        g_X[off] = v;
        g_Xbf0[off] = __float2bfloat16(v);
    }
}

// x fp32 -> xhi, xlo arrays
__global__ void conv_xsplit_kernel(const float* __restrict__ x) {
    size_t i = ((size_t)blockIdx.x * blockDim.x + threadIdx.x) * 4;
    float4 v = *(const float4*)(x + i);
    __nv_bfloat162 hi0, hi1, lo0, lo1;
    hi0.x = __float2bfloat16(v.x); lo0.x = __float2bfloat16(v.x - __bfloat162float(hi0.x));
    hi0.y = __float2bfloat16(v.y); lo0.y = __float2bfloat16(v.y - __bfloat162float(hi0.y));
    hi1.x = __float2bfloat16(v.z); lo1.x = __float2bfloat16(v.z - __bfloat162float(hi1.x));
    hi1.y = __float2bfloat16(v.w); lo1.y = __float2bfloat16(v.w - __bfloat162float(hi1.y));
    *(__nv_bfloat162*)(g_xhi + i)     = hi0;
    *(__nv_bfloat162*)(g_xhi + i + 2) = hi1;
    *(__nv_bfloat162*)(g_xlo + i)     = lo0;
    *(__nv_bfloat162*)(g_xlo + i + 2) = lo1;
}

// ---------------- mma.sync bf16 GEMM, segmented operands, 4-stage 1-barrier ----------------
// acc[m][n] = sum_k Aseg(kt>>11)[m][kt&2047] * Bseg(kt>>11)'[kt&2047][n]
//   BMODE 0: B K-major (row stride NN); BMODE 1: B row-major (row stride Ndim), trans ldmatrix
#define SK 40
#define ASZ (128*SK*2)
#define BSZ 10240
#define BT_STRIDE 272
#define NSTAGE 4
#define GSMEM (NSTAGE*(ASZ+BSZ))

template<int BMODE>
__global__ void __launch_bounds__(256, 2) mma_gemm_kernel(
    float* outF, __nv_bfloat16* outB, __nv_bfloat16* outBlo,
    const __nv_bfloat16* __restrict__ A0, const __nv_bfloat16* __restrict__ A1,
    const __nv_bfloat16* __restrict__ A2,
    const __nv_bfloat16* __restrict__ B0, const __nv_bfloat16* __restrict__ B1,
    const __nv_bfloat16* __restrict__ B2,
    const float* __restrict__ Dext, const float* __restrict__ bias,
    const float* __restrict__ coefp,
    int Ndim, int Kdim, float alpha, float beta, int addI)
{
    extern __shared__ __align__(16) char smem[];
    uint32_t sbase = smem_u32(smem);
    int tid = threadIdx.x;
    int wid = tid >> 5, lid = tid & 31;
    int warp_m = wid >> 2, warp_n = wid & 3;
    int bm = blockIdx.y * 128, bn = blockIdx.x * 128;

    float acc[4][4][4];
    #pragma unroll
    for (int i = 0; i < 4; i++)
        #pragma unroll
        for (int j = 0; j < 4; j++)
            #pragma unroll
            for (int r = 0; r < 4; r++) acc[i][j][r] = 0.f;

    auto load_stage = [&](int stage, int kt) {
        int seg = kt >> 11;
        int kc0 = kt & (NN - 1);
        const __nv_bfloat16* As = (seg == 0) ? A0 : ((seg == 1) ? A1 : A2);
        const __nv_bfloat16* Bs = (seg == 0) ? B0 : ((seg == 1) ? B1 : B2);
        uint32_t sA = sbase + stage * (ASZ + BSZ);
        uint32_t sB = sA + ASZ;
        #pragma unroll
        for (int s = 0; s < 2; s++) {
            int c = tid + s * 256;
            int row = c >> 2, kc = c & 3;
            const char* gA = (const char*)(As + (size_t)(bm + row) * NN + kc0 + kc * 8);
            uint32_t dA = sA + row * (SK*2) + kc * 16;
            asm volatile("cp.async.cg.shared.global [%0], [%1], 16;" :: "r"(dA), "l"(gA));
            if (BMODE == 0) {
                const char* gB = (const char*)(Bs + (size_t)(bn + row) * NN + kc0 + kc * 8);
                uint32_t dB = sB + row * (SK*2) + kc * 16;
                asm volatile("cp.async.cg.shared.global [%0], [%1], 16;" :: "r"(dB), "l"(gB));
            } else {
                int r = c >> 4, nch = c & 15;
                const char* gB = (const char*)(Bs + (size_t)(kc0 + r) * Ndim + bn + nch * 8);
                uint32_t dB = sB + r * BT_STRIDE + nch * 16;
                asm volatile("cp.async.cg.shared.global [%0], [%1], 16;" :: "r"(dB), "l"(gB));
            }
        }
        asm volatile("cp.async.commit_group;" ::: "memory");
    };

    const int NB = Kdim >> 5;
    #pragma unroll
    for (int s = 0; s < NSTAGE - 1; s++) load_stage(s, s * 32);

    uint32_t a_lane_off = (uint32_t)((lid & 15) * (SK*2) + ((lid >> 4) & 1) * 16);
    uint32_t b_lane_off0 = (uint32_t)((((lid & 7) + ((lid >> 4) & 1) * 8) * (SK*2)) + (((lid >> 3) & 1) * 16));
    int bg = lid >> 3, bw = lid & 7;
    uint32_t bt_krow = (uint32_t)((bg & 1) * 8 + bw);
    uint32_t bt_ncol = (uint32_t)((bg >> 1) * 8);

    for (int kb = 0; kb < NB; kb++) {
        if (kb >= NB - (NSTAGE - 1)) asm volatile("cp.async.wait_group 0;" ::: "memory");
        else                         asm volatile("cp.async.wait_group %0;" :: "n"(NSTAGE - 2) : "memory");
        __syncthreads();                    // single barrier per K-block

        int nkt = kb + NSTAGE - 1;
        if (nkt < NB) load_stage(nkt % NSTAGE, nkt * 32);   // overwrites stage (kb-1)%NSTAGE: safe post-barrier

        int stage = kb % NSTAGE;
        uint32_t sA = sbase + stage * (ASZ + BSZ) + warp_m * 64 * (SK*2);
        uint32_t sBb = sbase + stage * (ASZ + BSZ) + ASZ;

        #pragma unroll
        for (int kk = 0; kk < 2; kk++) {
            uint32_t af[4][4], bf[2][4];
            #pragma unroll
            for (int mi = 0; mi < 4; mi++) {
                uint32_t addr = sA + mi * 16 * (SK*2) + kk * 32 + a_lane_off;
                asm volatile("ldmatrix.sync.aligned.m8n8.x4.shared.b16 {%0,%1,%2,%3}, [%4];"
                    : "=r"(af[mi][0]), "=r"(af[mi][1]), "=r"(af[mi][2]), "=r"(af[mi][3]) : "r"(addr));
            }
            #pragma unroll
            for (int nj = 0; nj < 2; nj++) {
                if (BMODE == 0) {
                    uint32_t addr = sBb + (warp_n * 32 + nj * 16) * (SK*2) + kk * 32 + b_lane_off0;
                    asm volatile("ldmatrix.sync.aligned.m8n8.x4.shared.b16 {%0,%1,%2,%3}, [%4];"
                        : "=r"(bf[nj][0]), "=r"(bf[nj][1]), "=r"(bf[nj][2]), "=r"(bf[nj][3]) : "r"(addr));
                } else {
                    uint32_t addr = sBb + (kk * 16 + bt_krow) * BT_STRIDE
                                  + (warp_n * 32 + nj * 16 + bt_ncol) * 2;
                    asm volatile("ldmatrix.sync.aligned.m8n8.x4.trans.shared.b16 {%0,%1,%2,%3}, [%4];"
                        : "=r"(bf[nj][0]), "=r"(bf[nj][1]), "=r"(bf[nj][2]), "=r"(bf[nj][3]) : "r"(addr));
                }
            }
            #pragma unroll
            for (int mi = 0; mi < 4; mi++) {
                #pragma unroll
                for (int nj = 0; nj < 4; nj++) {
                    uint32_t b0 = bf[nj >> 1][(nj & 1) ? 2 : 0];
                    uint32_t b1 = bf[nj >> 1][(nj & 1) ? 3 : 1];
                    asm volatile(
                        "mma.sync.aligned.m16n8k16.row.col.f32.bf16.bf16.f32 "
                        "{%0,%1,%2,%3}, {%4,%5,%6,%7}, {%8,%9}, {%0,%1,%2,%3};"
                        : "+f"(acc[mi][nj][0]), "+f"(acc[mi][nj][1]),
                          "+f"(acc[mi][nj][2]), "+f"(acc[mi][nj][3])
                        : "r"(af[mi][0]), "r"(af[mi][1]), "r"(af[mi][2]), "r"(af[mi][3]),
                          "r"(b0), "r"(b1));
                }
            }
        }
    }

    if (coefp) { alpha = coefp[0]; beta = coefp[1]; }

    int lrow = lid >> 2, lcol = (lid & 3) * 2;
    #pragma unroll
    for (int mi = 0; mi < 4; mi++) {
        #pragma unroll
        for (int half = 0; half < 2; half++) {
            int row = bm + warp_m * 64 + mi * 16 + lrow + half * 8;
            #pragma unroll
            for (int nj = 0; nj < 4; nj++) {
                int col = bn + warp_n * 32 + nj * 8 + lcol;
                size_t off = (size_t)row * Ndim + col;
                float2 o;
                o.x = alpha * acc[mi][nj][half * 2 + 0];
                o.y = alpha * acc[mi][nj][half * 2 + 1];
                if (Dext) {
                    float2 d2 = *(const float2*)(Dext + off);
                    o.x += beta * d2.x; o.y += beta * d2.y;
                }
                if (bias) {
                    float2 b2 = *(const float2*)(bias + col);
                    o.x += b2.x; o.y += b2.y;
                }
                if (addI) {
                    if (row == col)     o.x += 1.f;
                    if (row == col + 1) o.y += 1.f;
                }
                if (outF) *(float2*)(outF + off) = o;
                if (outB || outBlo) {
                    __nv_bfloat162 h;
                    h.x = __float2bfloat16(o.x); h.y = __float2bfloat16(o.y);
                    if (outB) *(__nv_bfloat162*)(outB + off) = h;
                    if (outBlo) {
                        __nv_bfloat162 l;
                        l.x = __float2bfloat16(o.x - __bfloat162float(h.x));
                        l.y = __float2bfloat16(o.y - __bfloat162float(h.y));
                        *(__nv_bfloat162*)(outBlo + off) = l;
                    }
                }
            }
        }
    }
}

// ---------------- launch ----------------
extern "C" void kernel_launch(void* const* d_in, const int* in_sizes, int n_in,
                              void* d_out, int out_size) {
    const float* x      = (const float*)d_in[0];
    const float* weight = (const float*)d_in[1];
    const float* bias   = (const float*)d_in[2];
    float* out = (float*)d_out;

    float *pX, *pY, *pCoef;
    __nv_bfloat16 *pMbf, *pMlo, *pTbf, *pXb0, *pXb1, *pXl0, *pXl1, *pxhi, *pxlo;
    cudaGetSymbolAddress((void**)&pX, g_X);
    cudaGetSymbolAddress((void**)&pY, g_Y);
    cudaGetSymbolAddress((void**)&pCoef, g_coef);
    cudaGetSymbolAddress((void**)&pMbf, g_Mbf);
    cudaGetSymbolAddress((void**)&pMlo, g_Mlo);
    cudaGetSymbolAddress((void**)&pTbf, g_Tbf);
    cudaGetSymbolAddress((void**)&pXb0, g_Xbf0);
    cudaGetSymbolAddress((void**)&pXb1, g_Xbf1);
    cudaGetSymbolAddress((void**)&pXl0, g_Xlo0);
    cudaGetSymbolAddress((void**)&pXl1, g_Xlo1);
    cudaGetSymbolAddress((void**)&pxhi, g_xhi);
    cudaGetSymbolAddress((void**)&pxlo, g_xlo);

    cudaFuncSetAttribute(mma_gemm_kernel<0>, cudaFuncAttributeMaxDynamicSharedMemorySize, GSMEM);
    cudaFuncSetAttribute(mma_gemm_kernel<1>, cudaFuncAttributeMaxDynamicSharedMemorySize, GSMEM);

    // 1. M = I - (w - w^T)  (fp32 + bf16 hi/lo)
    build_M_kernel<<<dim3(NN/256, NN), 256>>>(weight);

    // 2. power iteration (4 pairs) -> sigma^2, c, schedule
    init_v_kernel<<<NN/256, 256>>>();
    for (int it = 0; it < 4; it++) {
        matvec_A_kernel<<<NN/8, 256>>>(1, 1.0f);
        matvec_A_kernel<<<NN/8, 256>>>(0, 1.0f / 64.0f);
    }
    matvec_A_kernel<<<NN/8, 256>>>(1, 1.0f);
    dots_and_c_kernel<<<1, 1024>>>();

    // 3. X0 = c * M^T (fp32 + bf16 hi)
    init_X0_kernel<<<dim3(NN/32, NN/32), dim3(32, 8)>>>();

    dim3 g2k(NN/128, NN/128);
    float *Xf = pX, *Xfn = pY;
    __nv_bfloat16 *Xb = pXb0, *Xbn = pXb1;
    __nv_bfloat16 *Xl = pXl0, *Xln = pXl1;

    // 4a. scaled Newton bf16, 5 iters (lo part only emitted on the last one)
    for (int it = 0; it < NSCALED; it++) {
        bool last = (it == NSCALED - 1);
        mma_gemm_kernel<1><<<g2k, 256, GSMEM>>>(nullptr, pTbf, nullptr,
                                                pMbf, pMbf, pMbf, Xb, Xb, Xb,
                                                nullptr, nullptr, nullptr,
                                                NN, NN, 1.0f, 0.0f, 0);          // T = M*Xb
        mma_gemm_kernel<1><<<g2k, 256, GSMEM>>>(Xfn, Xbn, last ? Xln : nullptr,
                                                Xb, Xb, Xb, pTbf, pTbf, pTbf,
                                                Xf, nullptr, pCoef + 2*it,
                                                NN, NN, 0.f, 0.f, 0);            // Xn = 2s*X - s^2*Xb*T
        float* tf = Xf; Xf = Xfn; Xfn = tf;
        __nv_bfloat16* tb = Xb; Xb = Xbn; Xbn = tb;
        if (last) { __nv_bfloat16* tl = Xl; Xl = Xln; Xln = tl; }
    }

    // 4b. single strengthened polish:
    //   R = I - M*X   (Mhi*Xhi + Mlo*Xhi + Mhi*Xlo, K=6144)
    mma_gemm_kernel<1><<<g2k, 256, GSMEM>>>(nullptr, pTbf, nullptr,
                                            pMbf, pMlo, pMbf, Xb, Xb, Xl,
                                            nullptr, nullptr, nullptr,
                                            NN, 3*NN, -1.0f, 0.0f, 1);
    //   X' = Xf + [Xhi|Xlo]*[R;R]  (K=4096) -> emit bf16 hi/lo only
    mma_gemm_kernel<1><<<g2k, 256, GSMEM>>>(nullptr, Xbn, Xln,
                                            Xb, Xl, Xl, pTbf, pTbf, pTbf,
                                            Xf, nullptr, nullptr,
                                            NN, 2*NN, 1.0f, 1.0f, 0);
    Xb = Xbn; Xl = Xln;

    // 5. out = 2*(x @ X^T) - x + bias   (segments: xhi*Xhi + xlo*Xhi + xhi*Xlo, K=6144)
    conv_xsplit_kernel<<<((size_t)MBIG*NN/4)/256, 256>>>(x);
    mma_gemm_kernel<0><<<dim3(NN/128, MBIG/128), 256, GSMEM>>>(out, nullptr, nullptr,
                                                               pxhi, pxlo, pxhi, Xb, Xb, Xl,
                                                               x, bias, nullptr,
                                                               NN, 3*NN, 2.0f, -1.0f, 0);
}